// round 6
// baseline (speedup 1.0000x reference)
#include <cuda_runtime.h>
#include <cuda_bf16.h>
#include <cstdint>

#define N_NODES 8192
#define D_IN    256
#define H_DIM   64
#define DEG     32
#define E_EDGES (N_NODES * DEG)

// Scratch: projected Q (fp32), K (bf16 packed pairs), V (fp32), x/W bf16 splits
__device__ float    g_Q[N_NODES * H_DIM];
__device__ uint32_t g_Kb[N_NODES * (H_DIM / 2)];   // bf16x2 per pair of dims
__device__ float    g_V[N_NODES * H_DIM];
__device__ __nv_bfloat16 g_xh[N_NODES * D_IN];
__device__ __nv_bfloat16 g_xl[N_NODES * D_IN];
__device__ __nv_bfloat16 g_Wh[192 * D_IN];
__device__ __nv_bfloat16 g_Wl[192 * D_IN];

// ===========================================================================
// helpers (plain sm_80-era PTX — compiles at compute_103 virtual target)
// ===========================================================================
__device__ __forceinline__ uint32_t smem_u32(const void* p) {
    uint32_t a;
    asm("{ .reg .u64 t; cvta.to.shared.u64 t, %1; cvt.u32.u64 %0, t; }"
        : "=r"(a) : "l"(p));
    return a;
}
__device__ __forceinline__ void cp_async16(uint32_t dst, const void* src) {
    asm volatile("cp.async.cg.shared.global [%0], [%1], 16;"
                 :: "r"(dst), "l"(src) : "memory");
}
__device__ __forceinline__ void ldmatrix_x4(uint32_t* r, uint32_t addr) {
    asm volatile("ldmatrix.sync.aligned.m8n8.x4.shared.b16 {%0,%1,%2,%3}, [%4];"
                 : "=r"(r[0]), "=r"(r[1]), "=r"(r[2]), "=r"(r[3]) : "r"(addr));
}
__device__ __forceinline__ void mma_bf16(float* c, const uint32_t* a, const uint32_t* b) {
    asm volatile(
        "mma.sync.aligned.m16n8k16.row.col.f32.bf16.bf16.f32 "
        "{%0,%1,%2,%3}, {%4,%5,%6,%7}, {%8,%9}, {%0,%1,%2,%3};"
        : "+f"(c[0]), "+f"(c[1]), "+f"(c[2]), "+f"(c[3])
        : "r"(a[0]), "r"(a[1]), "r"(a[2]), "r"(a[3]), "r"(b[0]), "r"(b[1]));
}

// ===========================================================================
// Kernel 0: split fp32 x / W into bf16 hi + lo. Grid-stride, high MLP.
// ===========================================================================
__device__ __forceinline__ void split_store4(__nv_bfloat16* hi, __nv_bfloat16* lo,
                                             float4 v) {
    float f[4] = {v.x, v.y, v.z, v.w};
    unsigned short hu[4], lu[4];
    #pragma unroll
    for (int i = 0; i < 4; i++) {
        __nv_bfloat16 hb = __float2bfloat16(f[i]);
        __nv_bfloat16 lb = __float2bfloat16(f[i] - __bfloat162float(hb));
        hu[i] = __bfloat16_as_ushort(hb);
        lu[i] = __bfloat16_as_ushort(lb);
    }
    *(uint2*)hi = make_uint2((uint32_t)hu[0] | ((uint32_t)hu[1] << 16),
                             (uint32_t)hu[2] | ((uint32_t)hu[3] << 16));
    *(uint2*)lo = make_uint2((uint32_t)lu[0] | ((uint32_t)lu[1] << 16),
                             (uint32_t)lu[2] | ((uint32_t)lu[3] << 16));
}

#define CONV_BLOCKS 256

__global__ __launch_bounds__(256) void convert_kernel(
    const float* __restrict__ x,
    const float* __restrict__ Wq, const float* __restrict__ Wk,
    const float* __restrict__ Wv)
{
    const int gtid = blockIdx.x * 256 + threadIdx.x;
    // W: 12288 float4s handled by the first 12288 threads
    if (gtid < 12288) {
        int base = gtid * 4;
        int row  = base >> 8;
        int c    = base & 255;
        const float* src = (row < 64)  ? &Wq[row * D_IN + c]
                         : (row < 128) ? &Wk[(row - 64) * D_IN + c]
                                       : &Wv[(row - 128) * D_IN + c];
        split_store4(&g_Wh[base], &g_Wl[base], *(const float4*)src);
    }
    // x: grid-stride over 524288 float4s (8 per thread)
    const int total = N_NODES * D_IN / 4;
    for (int idx = gtid; idx < total; idx += CONV_BLOCKS * 256) {
        float4 v = ((const float4*)x)[idx];
        split_store4(&g_xh[idx * 4], &g_xl[idx * 4], v);
    }
}

// ===========================================================================
// Kernel 1: QKV projection, bf16-split GEMM via mma.sync (m16n8k16).
//   3 passes: (xh,Wh), (xh,Wl), (xl,Wh). 3-stage cp.async pipeline.
// CTA: 64 rows x 192 cols, 256 threads, warp tile 32x48.
// ===========================================================================
#define LDS_B     144              // padded row stride in bytes (72 bf16)
#define A_BYTES   (64 * LDS_B)     // 9216
#define B_BYTES   (192 * LDS_B)    // 27648
#define STAGE_B   (A_BYTES + B_BYTES)
#define QKV_STAGES 3
#define QKV_SMEM  (QKV_STAGES * STAGE_B)   // 110592

__device__ __forceinline__ void qkv_issue_loads(
    int it, uint32_t sbase, int r0, int tid)
{
    const int pass = it >> 2;
    const int kk   = (it & 3) * 64;
    const __nv_bfloat16* A = (pass == 2) ? g_xl : g_xh;
    const __nv_bfloat16* B = (pass == 1) ? g_Wl : g_Wh;
    const uint32_t sa = sbase + (uint32_t)(it % QKV_STAGES) * STAGE_B;
    const uint32_t sb = sa + A_BYTES;
    #pragma unroll
    for (int t = 0; t < 2; t++) {                  // A: 512 x 16B
        int idx = tid + t * 256;
        int row = idx >> 3, c = idx & 7;
        cp_async16(sa + row * LDS_B + c * 16, A + (r0 + row) * D_IN + kk + c * 8);
    }
    #pragma unroll
    for (int t = 0; t < 6; t++) {                  // B: 1536 x 16B
        int idx = tid + t * 256;
        int row = idx >> 3, c = idx & 7;
        cp_async16(sb + row * LDS_B + c * 16, B + row * D_IN + kk + c * 8);
    }
    asm volatile("cp.async.commit_group;" ::: "memory");
}

__global__ __launch_bounds__(256) void qkv_mma_kernel(
    const float* __restrict__ bq, const float* __restrict__ bk)
{
    extern __shared__ __align__(16) char sm[];
    const int tid  = threadIdx.x;
    const int lane = tid & 31;
    const int wid  = tid >> 5;
    const int wm   = wid & 1;       // 2 M sub-tiles of 32
    const int wn   = wid >> 1;      // 4 N sub-tiles of 48
    const int r0   = blockIdx.x * 64;
    const uint32_t sbase = smem_u32(sm);

    float acc[2][6][4];
    #pragma unroll
    for (int mt = 0; mt < 2; mt++)
        #pragma unroll
        for (int nt = 0; nt < 6; nt++)
            #pragma unroll
            for (int q = 0; q < 4; q++) acc[mt][nt][q] = 0.f;

    qkv_issue_loads(0, sbase, r0, tid);
    qkv_issue_loads(1, sbase, r0, tid);

    #pragma unroll 1
    for (int it = 0; it < 12; it++) {
        if (it + 2 < 12) {
            asm volatile("cp.async.wait_group 1;" ::: "memory");
        } else {
            asm volatile("cp.async.wait_group 0;" ::: "memory");
        }
        __syncthreads();
        if (it + 2 < 12) qkv_issue_loads(it + 2, sbase, r0, tid);

        const uint32_t sa = sbase + (uint32_t)(it % QKV_STAGES) * STAGE_B;
        const uint32_t sb = sa + A_BYTES;
        #pragma unroll
        for (int ks = 0; ks < 4; ks++) {
            const int kb = ks * 16;
            uint32_t af[2][4];
            #pragma unroll
            for (int mt = 0; mt < 2; mt++) {
                int row = wm * 32 + mt * 16 + (lane & 15);
                uint32_t addr = sa + row * LDS_B + (kb + (lane >> 4) * 8) * 2;
                ldmatrix_x4(af[mt], addr);
            }
            uint32_t bfr[6][2];
            #pragma unroll
            for (int np = 0; np < 3; np++) {
                int row = wn * 48 + np * 16 + (lane >> 4) * 8 + (lane & 7);
                uint32_t addr = sb + row * LDS_B + (kb + ((lane >> 3) & 1) * 8) * 2;
                uint32_t r[4];
                ldmatrix_x4(r, addr);
                bfr[np * 2][0] = r[0]; bfr[np * 2][1] = r[1];
                bfr[np * 2 + 1][0] = r[2]; bfr[np * 2 + 1][1] = r[3];
            }
            #pragma unroll
            for (int mt = 0; mt < 2; mt++)
                #pragma unroll
                for (int nt = 0; nt < 6; nt++)
                    mma_bf16(acc[mt][nt], af[mt], bfr[nt]);
        }
        __syncthreads();
    }

    // epilogue: fragments -> g_Q (fp32+bias) / g_Kb (bf16 pairs+bias) / g_V
    const int grp = lane >> 2;
    const int qid = lane & 3;
    #pragma unroll
    for (int mt = 0; mt < 2; mt++) {
        int row0 = r0 + wm * 32 + mt * 16 + grp;
        #pragma unroll
        for (int nt = 0; nt < 6; nt++) {
            int cb  = wn * 48 + nt * 8;
            int h   = cb >> 6;
            int hc0 = (cb & 63) + qid * 2;
            if (h == 0) {
                float b0 = bq[hc0], b1 = bq[hc0 + 1];
                *(float2*)&g_Q[row0 * H_DIM + hc0] =
                    make_float2(acc[mt][nt][0] + b0, acc[mt][nt][1] + b1);
                *(float2*)&g_Q[(row0 + 8) * H_DIM + hc0] =
                    make_float2(acc[mt][nt][2] + b0, acc[mt][nt][3] + b1);
            } else if (h == 1) {
                float b0 = bk[hc0], b1 = bk[hc0 + 1];
                int pr = hc0 >> 1;
                __nv_bfloat162 k0 = __floats2bfloat162_rn(acc[mt][nt][0] + b0,
                                                          acc[mt][nt][1] + b1);
                __nv_bfloat162 k1 = __floats2bfloat162_rn(acc[mt][nt][2] + b0,
                                                          acc[mt][nt][3] + b1);
                g_Kb[row0 * 32 + pr]       = *(uint32_t*)&k0;
                g_Kb[(row0 + 8) * 32 + pr] = *(uint32_t*)&k1;
            } else {
                *(float2*)&g_V[row0 * H_DIM + hc0] =
                    make_float2(acc[mt][nt][0], acc[mt][nt][1]);
                *(float2*)&g_V[(row0 + 8) * H_DIM + hc0] =
                    make_float2(acc[mt][nt][2], acc[mt][nt][3]);
            }
        }
    }
}

// ===========================================================================
// Kernel 2: tiled sparse attention.
// CTA = 256 threads, NB=56 consecutive nodes (8 warps x 7 nodes), grid=147.
// Runtime check: if the block's neighbor offsets span <= 472 rows (true for
// this graph: 13*32 + 55 = 471), stage V fp32 + K bf16 into smem coalesced
// and serve all gathers from smem. Otherwise: generic gmem gather fallback.
// ===========================================================================
#define NB_ATT   56
#define ATT_CAP  472
#define SV_BYTES (ATT_CAP * H_DIM * 4)   // 120832 (stride 64 floats)
#define SK_BYTES (ATT_CAP * 128)         // 60416  (stride 128 bytes, 64 bf16)
#define ATT_SMEM (SV_BYTES + SK_BYTES)   // 181248
#define ATT_GRID ((N_NODES + NB_ATT - 1) / NB_ATT)

__device__ __forceinline__ float qk_dot8(float4 q0, float4 q1, uint4 kd) {
    __nv_bfloat162 b;
    float2 f;
    float part;
    b = *(__nv_bfloat162*)&kd.x; f = __bfloat1622float2(b);
    part  = q0.x * f.x + q0.y * f.y;
    b = *(__nv_bfloat162*)&kd.y; f = __bfloat1622float2(b);
    part += q0.z * f.x + q0.w * f.y;
    b = *(__nv_bfloat162*)&kd.z; f = __bfloat1622float2(b);
    part += q1.x * f.x + q1.y * f.y;
    b = *(__nv_bfloat162*)&kd.w; f = __bfloat1622float2(b);
    part += q1.z * f.x + q1.w * f.y;
    return part;
}

__global__ __launch_bounds__(256) void attn_tiled_kernel(
    const int*   __restrict__ edge_index,   // [2, E]: src then dst
    const int*   __restrict__ edge_type,    // [E]
    const float* __restrict__ ek_table,     // [16]
    float*       __restrict__ out)          // [N, 64]
{
    extern __shared__ __align__(16) char dynsm[];
    float* sV = (float*)dynsm;
    char*  sK = dynsm + SV_BYTES;
    __shared__ int s_maxoff;

    const int tid  = threadIdx.x;
    const int lane = tid & 31;
    const int w    = tid >> 5;
    const int i0   = blockIdx.x * NB_ATT;
    const int nb   = min(NB_ATT, N_NODES - i0);
    const int nedge = nb * DEG;

    if (tid == 0) s_maxoff = 0;
    __syncthreads();

    // block max neighbor offset
    int mymax = 0;
    for (int e = tid; e < nedge; e += 256) {
        int j = edge_index[E_EDGES + i0 * DEG + e];
        int off = (j - i0) & (N_NODES - 1);
        mymax = max(mymax, off);
    }
    #pragma unroll
    for (int o = 16; o > 0; o >>= 1)
        mymax = max(mymax, __shfl_xor_sync(0xffffffffu, mymax, o));
    if (lane == 0) atomicMax(&s_maxoff, mymax);
    __syncthreads();
    const int span = s_maxoff + 1;

    if (span <= ATT_CAP) {
        // ---- stage V (fp32) and K (bf16) rows [i0, i0+span) mod N ----
        for (int idx = tid; idx < span * 16; idx += 256) {
            int row = idx >> 4, c = idx & 15;
            float4 v = *(const float4*)&g_V[((i0 + row) & (N_NODES - 1)) * H_DIM + c * 4];
            *(float4*)&sV[row * 64 + c * 4] = v;
        }
        for (int idx = tid; idx < span * 8; idx += 256) {
            int row = idx >> 3, c = idx & 7;
            uint4 v = *(const uint4*)&g_Kb[((i0 + row) & (N_NODES - 1)) * 32 + c * 4];
            *(uint4*)(sK + row * 128 + c * 16) = v;
        }
        __syncthreads();

        for (int t = 0; t < 7; t++) {
            int ln = w * 7 + t;
            if (ln >= nb) break;
            const int i = i0 + ln;
            const int e = i * DEG + lane;
            const int j = edge_index[E_EDGES + e];
            const float ek = ek_table[edge_type[e]];

            const float4* Qp = (const float4*)&g_Q[i * H_DIM + (lane & 7) * 8];
            const float4 q0 = Qp[0], q1 = Qp[1];

            // scores: pass p covers neighbors 4p..4p+3; group g = lane>>3
            float s = 0.f;
            #pragma unroll
            for (int pass = 0; pass < 8; pass++) {
                int n  = pass * 4 + (lane >> 3);
                int jn = __shfl_sync(0xffffffffu, j, n);
                int off = (jn - i0) & (N_NODES - 1);
                uint4 kd = *(const uint4*)(sK + off * 128 + (lane & 7) * 16);
                float part = qk_dot8(q0, q1, kd);
                part += __shfl_xor_sync(0xffffffffu, part, 1);
                part += __shfl_xor_sync(0xffffffffu, part, 2);
                part += __shfl_xor_sync(0xffffffffu, part, 4);
                float st = __shfl_sync(0xffffffffu, part, (lane & 3) * 8);
                if (pass == (lane >> 2)) s = st;
            }
            s = (s + ek) * (1.0f / 512.0f);

            float m = s;
            #pragma unroll
            for (int o = 16; o > 0; o >>= 1)
                m = fmaxf(m, __shfl_xor_sync(0xffffffffu, m, o));
            const float pexp = __expf(s - m);
            float sum = pexp;
            #pragma unroll
            for (int o = 16; o > 0; o >>= 1)
                sum += __shfl_xor_sync(0xffffffffu, sum, o);
            const float p = pexp / sum;

            float a0 = 0.f, a1 = 0.f;
            #pragma unroll
            for (int n = 0; n < DEG; n++) {
                const float pn = __shfl_sync(0xffffffffu, p, n);
                const int   jn = __shfl_sync(0xffffffffu, j, n);
                const int  off = (jn - i0) & (N_NODES - 1);
                const float2 v = *(const float2*)&sV[off * 64 + lane * 2];
                a0 += pn * v.x;
                a1 += pn * v.y;
            }
            *(float2*)&out[i * H_DIM + lane * 2] = make_float2(a0, a1);
        }
    } else {
        // ---- generic gather fallback (same math, gmem addressing) ----
        for (int t = 0; t < 7; t++) {
            int ln = w * 7 + t;
            if (ln >= nb) break;
            const int i = i0 + ln;
            const int e = i * DEG + lane;
            const int j = edge_index[E_EDGES + e];
            const float ek = ek_table[edge_type[e]];

            const float4* Qp = (const float4*)&g_Q[i * H_DIM + (lane & 7) * 8];
            const float4 q0 = Qp[0], q1 = Qp[1];

            float s = 0.f;
            #pragma unroll
            for (int pass = 0; pass < 8; pass++) {
                int n  = pass * 4 + (lane >> 3);
                int jn = __shfl_sync(0xffffffffu, j, n);
                uint4 kd = *(const uint4*)&g_Kb[jn * 32 + (lane & 7) * 4];
                float part = qk_dot8(q0, q1, kd);
                part += __shfl_xor_sync(0xffffffffu, part, 1);
                part += __shfl_xor_sync(0xffffffffu, part, 2);
                part += __shfl_xor_sync(0xffffffffu, part, 4);
                float st = __shfl_sync(0xffffffffu, part, (lane & 3) * 8);
                if (pass == (lane >> 2)) s = st;
            }
            s = (s + ek) * (1.0f / 512.0f);

            float m = s;
            #pragma unroll
            for (int o = 16; o > 0; o >>= 1)
                m = fmaxf(m, __shfl_xor_sync(0xffffffffu, m, o));
            const float pexp = __expf(s - m);
            float sum = pexp;
            #pragma unroll
            for (int o = 16; o > 0; o >>= 1)
                sum += __shfl_xor_sync(0xffffffffu, sum, o);
            const float p = pexp / sum;

            float a0 = 0.f, a1 = 0.f;
            #pragma unroll
            for (int n = 0; n < DEG; n++) {
                const float pn = __shfl_sync(0xffffffffu, p, n);
                const int   jn = __shfl_sync(0xffffffffu, j, n);
                const float2 v = *(const float2*)&g_V[jn * H_DIM + lane * 2];
                a0 += pn * v.x;
                a1 += pn * v.y;
            }
            *(float2*)&out[i * H_DIM + lane * 2] = make_float2(a0, a1);
        }
    }
}

// ---------------------------------------------------------------------------
extern "C" void kernel_launch(void* const* d_in, const int* in_sizes, int n_in,
                              void* d_out, int out_size)
{
    const float* x          = (const float*)d_in[0];
    // d_in[1] = adj — intentionally unused (edge list is exact)
    const int*   edge_index = (const int*)d_in[2];
    const int*   edge_type  = (const int*)d_in[3];
    const float* Wq         = (const float*)d_in[4];
    const float* bq         = (const float*)d_in[5];
    const float* Wk         = (const float*)d_in[6];
    const float* bk         = (const float*)d_in[7];
    const float* Wv         = (const float*)d_in[8];
    const float* ekt        = (const float*)d_in[9];
    float*       out        = (float*)d_out;

    static bool attr_set = false;
    if (!attr_set) {
        cudaFuncSetAttribute(qkv_mma_kernel,
                             cudaFuncAttributeMaxDynamicSharedMemorySize, QKV_SMEM);
        cudaFuncSetAttribute(attn_tiled_kernel,
                             cudaFuncAttributeMaxDynamicSharedMemorySize, ATT_SMEM);
        attr_set = true;
    }

    convert_kernel<<<CONV_BLOCKS, 256>>>(x, Wq, Wk, Wv);
    qkv_mma_kernel<<<N_NODES / 64, 256, QKV_SMEM>>>(bq, bk);
    attn_tiled_kernel<<<ATT_GRID, 256, ATT_SMEM>>>(edge_index, edge_type, ekt, out);
}

// round 7
// speedup vs baseline: 1.2626x; 1.2626x over previous
#include <cuda_runtime.h>
#include <cuda_bf16.h>
#include <cstdint>

#define N_NODES 8192
#define D_IN    256
#define H_DIM   64
#define DEG     32
#define E_EDGES (N_NODES * DEG)

// Scratch: projected Q/K/V (fp32) + bf16 hi/lo split of W only
__device__ float g_Q[N_NODES * H_DIM];
__device__ float g_K[N_NODES * H_DIM];
__device__ float g_V[N_NODES * H_DIM];
__device__ __nv_bfloat16 g_Wh[192 * D_IN];
__device__ __nv_bfloat16 g_Wl[192 * D_IN];

// ===========================================================================
// helpers (plain sm_80-era PTX — compiles at compute_103 virtual target)
// ===========================================================================
__device__ __forceinline__ uint32_t smem_u32(const void* p) {
    uint32_t a;
    asm("{ .reg .u64 t; cvta.to.shared.u64 t, %1; cvt.u32.u64 %0, t; }"
        : "=r"(a) : "l"(p));
    return a;
}
__device__ __forceinline__ void cp_async16(uint32_t dst, const void* src) {
    asm volatile("cp.async.cg.shared.global [%0], [%1], 16;"
                 :: "r"(dst), "l"(src) : "memory");
}
__device__ __forceinline__ void ldmatrix_x4(uint32_t* r, uint32_t addr) {
    asm volatile("ldmatrix.sync.aligned.m8n8.x4.shared.b16 {%0,%1,%2,%3}, [%4];"
                 : "=r"(r[0]), "=r"(r[1]), "=r"(r[2]), "=r"(r[3]) : "r"(addr));
}
__device__ __forceinline__ void mma_bf16(float* c, const uint32_t* a, const uint32_t* b) {
    asm volatile(
        "mma.sync.aligned.m16n8k16.row.col.f32.bf16.bf16.f32 "
        "{%0,%1,%2,%3}, {%4,%5,%6,%7}, {%8,%9}, {%0,%1,%2,%3};"
        : "+f"(c[0]), "+f"(c[1]), "+f"(c[2]), "+f"(c[3])
        : "r"(a[0]), "r"(a[1]), "r"(a[2]), "r"(a[3]), "r"(b[0]), "r"(b[1]));
}

// split a float4 into packed bf16 hi (uint2) + lo (uint2)
__device__ __forceinline__ void split4(float4 v, uint2& hv, uint2& lv) {
    float f[4] = {v.x, v.y, v.z, v.w};
    unsigned short hu[4], lu[4];
    #pragma unroll
    for (int i = 0; i < 4; i++) {
        __nv_bfloat16 hb = __float2bfloat16(f[i]);
        __nv_bfloat16 lb = __float2bfloat16(f[i] - __bfloat162float(hb));
        hu[i] = __bfloat16_as_ushort(hb);
        lu[i] = __bfloat16_as_ushort(lb);
    }
    hv = make_uint2((uint32_t)hu[0] | ((uint32_t)hu[1] << 16),
                    (uint32_t)hu[2] | ((uint32_t)hu[3] << 16));
    lv = make_uint2((uint32_t)lu[0] | ((uint32_t)lu[1] << 16),
                    (uint32_t)lu[2] | ((uint32_t)lu[3] << 16));
}

// ===========================================================================
// Kernel 0: split W (fp32) into bf16 hi + lo.  12288 float4s, 48 blocks.
// ===========================================================================
__global__ __launch_bounds__(256) void wconv_kernel(
    const float* __restrict__ Wq, const float* __restrict__ Wk,
    const float* __restrict__ Wv)
{
    const int gtid = blockIdx.x * 256 + threadIdx.x;   // 0..12287
    const int base = gtid * 4;
    const int row  = base >> 8;
    const int c    = base & 255;
    const float* src = (row < 64)  ? &Wq[row * D_IN + c]
                     : (row < 128) ? &Wk[(row - 64) * D_IN + c]
                                   : &Wv[(row - 128) * D_IN + c];
    uint2 hv, lv;
    split4(*(const float4*)src, hv, lv);
    *(uint2*)&g_Wh[base] = hv;
    *(uint2*)&g_Wl[base] = lv;
}

// ===========================================================================
// Kernel 1: QKV projection, bf16-split GEMM via mma.sync (m16n8k16).
//   x loaded fp32 + split to hi/lo IN-KERNEL (no x pre-convert pass).
//   Per K-chunk (64): D += Ah*Bh + Ah*Bl + Al*Bh, fp32 accum.
// CTA: 64 rows x 192 cols, 256 threads, warp tile 32x48, 4 chunks,
// double-buffered A(hi/lo, STS from regs) + B(cp.async from g_Wh/g_Wl).
// ===========================================================================
#define LDS_B     144               // padded row stride in bytes (72 bf16)
#define A_ONE     (64 * LDS_B)      // 9216  (one of hi/lo)
#define A_BUF     (2 * A_ONE)       // 18432 (hi + lo)
#define B_ONE     (192 * LDS_B)     // 27648
#define B_STAGE   (2 * B_ONE)       // 55296 (hi + lo)
#define B_OFF     (2 * A_BUF)       // 36864
#define QKV_SMEM  (B_OFF + 2 * B_STAGE)   // 147456

__device__ __forceinline__ void ld_a(const float* __restrict__ x,
                                     int it, int r0, int tid, float4* r) {
    const int kk = it * 64;
    #pragma unroll
    for (int t = 0; t < 4; t++) {
        int idx = tid + t * 256;       // 0..1023
        int row = idx >> 4, c4 = idx & 15;
        r[t] = *(const float4*)&x[(r0 + row) * D_IN + kk + c4 * 4];
    }
}
__device__ __forceinline__ void st_a(uint32_t abuf, int tid, const float4* r) {
    #pragma unroll
    for (int t = 0; t < 4; t++) {
        int idx = tid + t * 256;
        int row = idx >> 4, c4 = idx & 15;
        uint32_t off = (uint32_t)(row * LDS_B + c4 * 8);
        uint2 hv, lv;
        split4(r[t], hv, lv);
        asm volatile("st.shared.v2.b32 [%0], {%1, %2};"
                     :: "r"(abuf + off), "r"(hv.x), "r"(hv.y) : "memory");
        asm volatile("st.shared.v2.b32 [%0], {%1, %2};"
                     :: "r"(abuf + A_ONE + off), "r"(lv.x), "r"(lv.y) : "memory");
    }
}
__device__ __forceinline__ void issue_b(int it, uint32_t sbase, int tid) {
    const int kk = it * 64;
    const uint32_t sb = sbase + B_OFF + (uint32_t)(it & 1) * B_STAGE;
    #pragma unroll
    for (int t = 0; t < 6; t++) {                  // Bh: 1536 x 16B
        int idx = tid + t * 256;
        int row = idx >> 3, c = idx & 7;
        cp_async16(sb + row * LDS_B + c * 16, g_Wh + row * D_IN + kk + c * 8);
    }
    #pragma unroll
    for (int t = 0; t < 6; t++) {                  // Bl: 1536 x 16B
        int idx = tid + t * 256;
        int row = idx >> 3, c = idx & 7;
        cp_async16(sb + B_ONE + row * LDS_B + c * 16, g_Wl + row * D_IN + kk + c * 8);
    }
    asm volatile("cp.async.commit_group;" ::: "memory");
}

__global__ __launch_bounds__(256) void qkv_mma_kernel(
    const float* __restrict__ x,
    const float* __restrict__ bq, const float* __restrict__ bk)
{
    extern __shared__ __align__(16) char sm[];
    const int tid  = threadIdx.x;
    const int lane = tid & 31;
    const int wid  = tid >> 5;
    const int wm   = wid & 1;       // 2 M sub-tiles of 32
    const int wn   = wid >> 1;      // 4 N sub-tiles of 48
    const int r0   = blockIdx.x * 64;
    const uint32_t sbase = smem_u32(sm);

    float acc[2][6][4];
    #pragma unroll
    for (int mt = 0; mt < 2; mt++)
        #pragma unroll
        for (int nt = 0; nt < 6; nt++)
            #pragma unroll
            for (int q = 0; q < 4; q++) acc[mt][nt][q] = 0.f;

    float4 ra[4];
    // prologue: A(0) -> buf0, A(1) held in regs; B(0), B(1) in flight
    ld_a(x, 0, r0, tid, ra);
    issue_b(0, sbase, tid);
    st_a(sbase, tid, ra);
    ld_a(x, 1, r0, tid, ra);
    issue_b(1, sbase, tid);
    asm volatile("cp.async.wait_group 1;" ::: "memory");
    __syncthreads();

    #pragma unroll 1
    for (int it = 0; it < 4; it++) {
        const uint32_t sa_h = sbase + (uint32_t)(it & 1) * A_BUF;
        const uint32_t sa_l = sa_h + A_ONE;
        const uint32_t sb_h = sbase + B_OFF + (uint32_t)(it & 1) * B_STAGE;
        const uint32_t sb_l = sb_h + B_ONE;

        #pragma unroll
        for (int ks = 0; ks < 4; ks++) {
            const int kb = ks * 16;
            const uint32_t acol = (uint32_t)((kb + (lane >> 4) * 8) * 2);
            uint32_t ah[2][4], al[2][4];
            #pragma unroll
            for (int mt = 0; mt < 2; mt++) {
                int row = wm * 32 + mt * 16 + (lane & 15);
                ldmatrix_x4(ah[mt], sa_h + row * LDS_B + acol);
                ldmatrix_x4(al[mt], sa_l + row * LDS_B + acol);
            }
            uint32_t bh[6][2], bl[6][2];
            const uint32_t bcol = (uint32_t)((kb + ((lane >> 3) & 1) * 8) * 2);
            #pragma unroll
            for (int np = 0; np < 3; np++) {
                int row = wn * 48 + np * 16 + (lane >> 4) * 8 + (lane & 7);
                uint32_t r[4];
                ldmatrix_x4(r, sb_h + row * LDS_B + bcol);
                bh[np * 2][0] = r[0]; bh[np * 2][1] = r[1];
                bh[np * 2 + 1][0] = r[2]; bh[np * 2 + 1][1] = r[3];
                ldmatrix_x4(r, sb_l + row * LDS_B + bcol);
                bl[np * 2][0] = r[0]; bl[np * 2][1] = r[1];
                bl[np * 2 + 1][0] = r[2]; bl[np * 2 + 1][1] = r[3];
            }
            #pragma unroll
            for (int mt = 0; mt < 2; mt++)
                #pragma unroll
                for (int nt = 0; nt < 6; nt++) {
                    mma_bf16(acc[mt][nt], ah[mt], bh[nt]);
                    mma_bf16(acc[mt][nt], ah[mt], bl[nt]);
                    mma_bf16(acc[mt][nt], al[mt], bh[nt]);
                }
        }
        __syncthreads();

        if (it < 3) {
            st_a(sbase + (uint32_t)((it + 1) & 1) * A_BUF, tid, ra);
            if (it < 2) {
                ld_a(x, it + 2, r0, tid, ra);
                issue_b(it + 2, sbase, tid);
                asm volatile("cp.async.wait_group 1;" ::: "memory");
            } else {
                asm volatile("cp.async.wait_group 0;" ::: "memory");
            }
            __syncthreads();
        }
    }

    // epilogue: fragments -> g_Q / g_K / g_V with bias (all fp32)
    const int grp = lane >> 2;
    const int qid = lane & 3;
    #pragma unroll
    for (int mt = 0; mt < 2; mt++) {
        int row0 = r0 + wm * 32 + mt * 16 + grp;
        #pragma unroll
        for (int nt = 0; nt < 6; nt++) {
            int cb  = wn * 48 + nt * 8;
            int h   = cb >> 6;
            int hc0 = (cb & 63) + qid * 2;
            float* dst;
            float b0, b1;
            if (h == 0)      { dst = g_Q; b0 = bq[hc0]; b1 = bq[hc0 + 1]; }
            else if (h == 1) { dst = g_K; b0 = bk[hc0]; b1 = bk[hc0 + 1]; }
            else             { dst = g_V; b0 = 0.f;     b1 = 0.f; }
            *(float2*)&dst[row0 * H_DIM + hc0] =
                make_float2(acc[mt][nt][0] + b0, acc[mt][nt][1] + b1);
            *(float2*)&dst[(row0 + 8) * H_DIM + hc0] =
                make_float2(acc[mt][nt][2] + b0, acc[mt][nt][3] + b1);
        }
    }
}

// ---------------------------------------------------------------------------
// Kernel 2: sparse attention. One warp per node. No shared memory.
// (round-3 version — known 17.6us)
// ---------------------------------------------------------------------------
#define ATT_WARPS 8

__global__ __launch_bounds__(ATT_WARPS * 32) void attn_kernel(
    const int*   __restrict__ edge_index,   // [2, E]: src then dst
    const int*   __restrict__ edge_type,    // [E]
    const float* __restrict__ ek_table,     // [16]
    float*       __restrict__ out)          // [N, 64]
{
    const int lane = threadIdx.x & 31;
    const int i    = blockIdx.x * ATT_WARPS + (threadIdx.x >> 5);
    const int e    = i * DEG + lane;

    const int   j  = edge_index[E_EDGES + e];     // dst neighbor of node i
    const float ek = ek_table[edge_type[e]];

    const int dc = (lane >> 2) * 8;
    const float4 q0 = *(const float4*)&g_Q[i * H_DIM + dc];
    const float4 q1 = *(const float4*)&g_Q[i * H_DIM + dc + 4];

    float s = 0.f;
    #pragma unroll
    for (int pass = 0; pass < 8; pass++) {
        const int n  = pass * 4 + (lane & 3);
        const int jn = __shfl_sync(0xffffffffu, j, n);
        const float4* Kp = (const float4*)&g_K[jn * H_DIM + dc];
        const float4 k0 = Kp[0];
        const float4 k1 = Kp[1];
        float part = q0.x * k0.x + q0.y * k0.y + q0.z * k0.z + q0.w * k0.w
                   + q1.x * k1.x + q1.y * k1.y + q1.z * k1.z + q1.w * k1.w;
        part += __shfl_xor_sync(0xffffffffu, part, 4);
        part += __shfl_xor_sync(0xffffffffu, part, 8);
        part += __shfl_xor_sync(0xffffffffu, part, 16);
        if (pass == (lane >> 2)) s = part;
    }
    s = (s + ek) * (1.0f / 512.0f);

    float m = s;
    #pragma unroll
    for (int o = 16; o > 0; o >>= 1) m = fmaxf(m, __shfl_xor_sync(0xffffffffu, m, o));
    const float pexp = __expf(s - m);
    float sum = pexp;
    #pragma unroll
    for (int o = 16; o > 0; o >>= 1) sum += __shfl_xor_sync(0xffffffffu, sum, o);
    const float p = pexp / sum;

    float a0 = 0.f, a1 = 0.f;
    #pragma unroll
    for (int n = 0; n < DEG; n++) {
        const float pn = __shfl_sync(0xffffffffu, p, n);
        const int   jn = __shfl_sync(0xffffffffu, j, n);
        const float2 v = *(const float2*)&g_V[jn * H_DIM + lane * 2];
        a0 += pn * v.x;
        a1 += pn * v.y;
    }
    *(float2*)&out[i * H_DIM + lane * 2] = make_float2(a0, a1);
}

// ---------------------------------------------------------------------------
extern "C" void kernel_launch(void* const* d_in, const int* in_sizes, int n_in,
                              void* d_out, int out_size)
{
    const float* x          = (const float*)d_in[0];
    // d_in[1] = adj — intentionally unused (edge list is exact)
    const int*   edge_index = (const int*)d_in[2];
    const int*   edge_type  = (const int*)d_in[3];
    const float* Wq         = (const float*)d_in[4];
    const float* bq         = (const float*)d_in[5];
    const float* Wk         = (const float*)d_in[6];
    const float* bk         = (const float*)d_in[7];
    const float* Wv         = (const float*)d_in[8];
    const float* ekt        = (const float*)d_in[9];
    float*       out        = (float*)d_out;

    static bool attr_set = false;
    if (!attr_set) {
        cudaFuncSetAttribute(qkv_mma_kernel,
                             cudaFuncAttributeMaxDynamicSharedMemorySize, QKV_SMEM);
        attr_set = true;
    }

    wconv_kernel<<<48, 256>>>(Wq, Wk, Wv);
    qkv_mma_kernel<<<N_NODES / 64, 256, QKV_SMEM>>>(x, bq, bk);
    attn_kernel<<<N_NODES / ATT_WARPS, ATT_WARPS * 32>>>(edge_index, edge_type, ekt, out);
}

// round 8
// speedup vs baseline: 1.3513x; 1.0703x over previous
#include <cuda_runtime.h>
#include <cuda_bf16.h>
#include <cstdint>

#define N_NODES 8192
#define D_IN    256
#define H_DIM   64
#define DEG     32
#define E_EDGES (N_NODES * DEG)

// Scratch: projected Q/V (fp32), K (packed bf16 pairs), W bf16 hi/lo split
__device__ float    g_Q[N_NODES * H_DIM];
__device__ uint32_t g_Kb[N_NODES * (H_DIM / 2)];   // bf16x2 per pair of dims
__device__ float    g_V[N_NODES * H_DIM];
__device__ __nv_bfloat16 g_Wh[192 * D_IN];
__device__ __nv_bfloat16 g_Wl[192 * D_IN];

// ===========================================================================
// helpers (plain sm_80-era PTX — compiles at compute_103 virtual target)
// ===========================================================================
__device__ __forceinline__ uint32_t smem_u32(const void* p) {
    uint32_t a;
    asm("{ .reg .u64 t; cvta.to.shared.u64 t, %1; cvt.u32.u64 %0, t; }"
        : "=r"(a) : "l"(p));
    return a;
}
__device__ __forceinline__ void cp_async16(uint32_t dst, const void* src) {
    asm volatile("cp.async.cg.shared.global [%0], [%1], 16;"
                 :: "r"(dst), "l"(src) : "memory");
}
__device__ __forceinline__ void ldmatrix_x4(uint32_t* r, uint32_t addr) {
    asm volatile("ldmatrix.sync.aligned.m8n8.x4.shared.b16 {%0,%1,%2,%3}, [%4];"
                 : "=r"(r[0]), "=r"(r[1]), "=r"(r[2]), "=r"(r[3]) : "r"(addr));
}
__device__ __forceinline__ void mma_bf16(float* c, const uint32_t* a, const uint32_t* b) {
    asm volatile(
        "mma.sync.aligned.m16n8k16.row.col.f32.bf16.bf16.f32 "
        "{%0,%1,%2,%3}, {%4,%5,%6,%7}, {%8,%9}, {%0,%1,%2,%3};"
        : "+f"(c[0]), "+f"(c[1]), "+f"(c[2]), "+f"(c[3])
        : "r"(a[0]), "r"(a[1]), "r"(a[2]), "r"(a[3]), "r"(b[0]), "r"(b[1]));
}

// split a float4 into packed bf16 hi (uint2) + lo (uint2)
__device__ __forceinline__ void split4(float4 v, uint2& hv, uint2& lv) {
    float f[4] = {v.x, v.y, v.z, v.w};
    unsigned short hu[4], lu[4];
    #pragma unroll
    for (int i = 0; i < 4; i++) {
        __nv_bfloat16 hb = __float2bfloat16(f[i]);
        __nv_bfloat16 lb = __float2bfloat16(f[i] - __bfloat162float(hb));
        hu[i] = __bfloat16_as_ushort(hb);
        lu[i] = __bfloat16_as_ushort(lb);
    }
    hv = make_uint2((uint32_t)hu[0] | ((uint32_t)hu[1] << 16),
                    (uint32_t)hu[2] | ((uint32_t)hu[3] << 16));
    lv = make_uint2((uint32_t)lu[0] | ((uint32_t)lu[1] << 16),
                    (uint32_t)lu[2] | ((uint32_t)lu[3] << 16));
}

// ===========================================================================
// Kernel 0: split W (fp32) into bf16 hi + lo.  12288 float4s, 48 blocks.
// ===========================================================================
__global__ __launch_bounds__(256) void wconv_kernel(
    const float* __restrict__ Wq, const float* __restrict__ Wk,
    const float* __restrict__ Wv)
{
    const int gtid = blockIdx.x * 256 + threadIdx.x;   // 0..12287
    const int base = gtid * 4;
    const int row  = base >> 8;
    const int c    = base & 255;
    const float* src = (row < 64)  ? &Wq[row * D_IN + c]
                     : (row < 128) ? &Wk[(row - 64) * D_IN + c]
                                   : &Wv[(row - 128) * D_IN + c];
    uint2 hv, lv;
    split4(*(const float4*)src, hv, lv);
    *(uint2*)&g_Wh[base] = hv;
    *(uint2*)&g_Wl[base] = lv;
}

// ===========================================================================
// Kernel 1: QKV projection, bf16-split GEMM via mma.sync (m16n8k16).
//   x loaded fp32 + split to hi/lo in-kernel. (unchanged from round 7,
//   except K is now written packed bf16 to g_Kb)
// ===========================================================================
#define LDS_B     144               // padded row stride in bytes (72 bf16)
#define A_ONE     (64 * LDS_B)      // 9216  (one of hi/lo)
#define A_BUF     (2 * A_ONE)       // 18432 (hi + lo)
#define B_ONE     (192 * LDS_B)     // 27648
#define B_STAGE   (2 * B_ONE)       // 55296 (hi + lo)
#define B_OFF     (2 * A_BUF)       // 36864
#define QKV_SMEM  (B_OFF + 2 * B_STAGE)   // 147456

__device__ __forceinline__ void ld_a(const float* __restrict__ x,
                                     int it, int r0, int tid, float4* r) {
    const int kk = it * 64;
    #pragma unroll
    for (int t = 0; t < 4; t++) {
        int idx = tid + t * 256;       // 0..1023
        int row = idx >> 4, c4 = idx & 15;
        r[t] = *(const float4*)&x[(r0 + row) * D_IN + kk + c4 * 4];
    }
}
__device__ __forceinline__ void st_a(uint32_t abuf, int tid, const float4* r) {
    #pragma unroll
    for (int t = 0; t < 4; t++) {
        int idx = tid + t * 256;
        int row = idx >> 4, c4 = idx & 15;
        uint32_t off = (uint32_t)(row * LDS_B + c4 * 8);
        uint2 hv, lv;
        split4(r[t], hv, lv);
        asm volatile("st.shared.v2.b32 [%0], {%1, %2};"
                     :: "r"(abuf + off), "r"(hv.x), "r"(hv.y) : "memory");
        asm volatile("st.shared.v2.b32 [%0], {%1, %2};"
                     :: "r"(abuf + A_ONE + off), "r"(lv.x), "r"(lv.y) : "memory");
    }
}
__device__ __forceinline__ void issue_b(int it, uint32_t sbase, int tid) {
    const int kk = it * 64;
    const uint32_t sb = sbase + B_OFF + (uint32_t)(it & 1) * B_STAGE;
    #pragma unroll
    for (int t = 0; t < 6; t++) {                  // Bh: 1536 x 16B
        int idx = tid + t * 256;
        int row = idx >> 3, c = idx & 7;
        cp_async16(sb + row * LDS_B + c * 16, g_Wh + row * D_IN + kk + c * 8);
    }
    #pragma unroll
    for (int t = 0; t < 6; t++) {                  // Bl: 1536 x 16B
        int idx = tid + t * 256;
        int row = idx >> 3, c = idx & 7;
        cp_async16(sb + B_ONE + row * LDS_B + c * 16, g_Wl + row * D_IN + kk + c * 8);
    }
    asm volatile("cp.async.commit_group;" ::: "memory");
}

__global__ __launch_bounds__(256) void qkv_mma_kernel(
    const float* __restrict__ x,
    const float* __restrict__ bq, const float* __restrict__ bk)
{
    extern __shared__ __align__(16) char sm[];
    const int tid  = threadIdx.x;
    const int lane = tid & 31;
    const int wid  = tid >> 5;
    const int wm   = wid & 1;       // 2 M sub-tiles of 32
    const int wn   = wid >> 1;      // 4 N sub-tiles of 48
    const int r0   = blockIdx.x * 64;
    const uint32_t sbase = smem_u32(sm);

    float acc[2][6][4];
    #pragma unroll
    for (int mt = 0; mt < 2; mt++)
        #pragma unroll
        for (int nt = 0; nt < 6; nt++)
            #pragma unroll
            for (int q = 0; q < 4; q++) acc[mt][nt][q] = 0.f;

    float4 ra[4];
    ld_a(x, 0, r0, tid, ra);
    issue_b(0, sbase, tid);
    st_a(sbase, tid, ra);
    ld_a(x, 1, r0, tid, ra);
    issue_b(1, sbase, tid);
    asm volatile("cp.async.wait_group 1;" ::: "memory");
    __syncthreads();

    #pragma unroll 1
    for (int it = 0; it < 4; it++) {
        const uint32_t sa_h = sbase + (uint32_t)(it & 1) * A_BUF;
        const uint32_t sa_l = sa_h + A_ONE;
        const uint32_t sb_h = sbase + B_OFF + (uint32_t)(it & 1) * B_STAGE;
        const uint32_t sb_l = sb_h + B_ONE;

        #pragma unroll
        for (int ks = 0; ks < 4; ks++) {
            const int kb = ks * 16;
            const uint32_t acol = (uint32_t)((kb + (lane >> 4) * 8) * 2);
            uint32_t ah[2][4], al[2][4];
            #pragma unroll
            for (int mt = 0; mt < 2; mt++) {
                int row = wm * 32 + mt * 16 + (lane & 15);
                ldmatrix_x4(ah[mt], sa_h + row * LDS_B + acol);
                ldmatrix_x4(al[mt], sa_l + row * LDS_B + acol);
            }
            uint32_t bh[6][2], bl[6][2];
            const uint32_t bcol = (uint32_t)((kb + ((lane >> 3) & 1) * 8) * 2);
            #pragma unroll
            for (int np = 0; np < 3; np++) {
                int row = wn * 48 + np * 16 + (lane >> 4) * 8 + (lane & 7);
                uint32_t r[4];
                ldmatrix_x4(r, sb_h + row * LDS_B + bcol);
                bh[np * 2][0] = r[0]; bh[np * 2][1] = r[1];
                bh[np * 2 + 1][0] = r[2]; bh[np * 2 + 1][1] = r[3];
                ldmatrix_x4(r, sb_l + row * LDS_B + bcol);
                bl[np * 2][0] = r[0]; bl[np * 2][1] = r[1];
                bl[np * 2 + 1][0] = r[2]; bl[np * 2 + 1][1] = r[3];
            }
            #pragma unroll
            for (int mt = 0; mt < 2; mt++)
                #pragma unroll
                for (int nt = 0; nt < 6; nt++) {
                    mma_bf16(acc[mt][nt], ah[mt], bh[nt]);
                    mma_bf16(acc[mt][nt], ah[mt], bl[nt]);
                    mma_bf16(acc[mt][nt], al[mt], bh[nt]);
                }
        }
        __syncthreads();

        if (it < 3) {
            st_a(sbase + (uint32_t)((it + 1) & 1) * A_BUF, tid, ra);
            if (it < 2) {
                ld_a(x, it + 2, r0, tid, ra);
                issue_b(it + 2, sbase, tid);
                asm volatile("cp.async.wait_group 1;" ::: "memory");
            } else {
                asm volatile("cp.async.wait_group 0;" ::: "memory");
            }
            __syncthreads();
        }
    }

    // epilogue: fragments -> g_Q (fp32+bias) / g_Kb (bf16 pairs+bias) / g_V
    const int grp = lane >> 2;
    const int qid = lane & 3;
    #pragma unroll
    for (int mt = 0; mt < 2; mt++) {
        int row0 = r0 + wm * 32 + mt * 16 + grp;
        #pragma unroll
        for (int nt = 0; nt < 6; nt++) {
            int cb  = wn * 48 + nt * 8;
            int h   = cb >> 6;
            int hc0 = (cb & 63) + qid * 2;
            if (h == 0) {
                float b0 = bq[hc0], b1 = bq[hc0 + 1];
                *(float2*)&g_Q[row0 * H_DIM + hc0] =
                    make_float2(acc[mt][nt][0] + b0, acc[mt][nt][1] + b1);
                *(float2*)&g_Q[(row0 + 8) * H_DIM + hc0] =
                    make_float2(acc[mt][nt][2] + b0, acc[mt][nt][3] + b1);
            } else if (h == 1) {
                float b0 = bk[hc0], b1 = bk[hc0 + 1];
                int pr = hc0 >> 1;
                __nv_bfloat162 k0 = __floats2bfloat162_rn(acc[mt][nt][0] + b0,
                                                          acc[mt][nt][1] + b1);
                __nv_bfloat162 k1 = __floats2bfloat162_rn(acc[mt][nt][2] + b0,
                                                          acc[mt][nt][3] + b1);
                g_Kb[row0 * 32 + pr]       = *(uint32_t*)&k0;
                g_Kb[(row0 + 8) * 32 + pr] = *(uint32_t*)&k1;
            } else {
                *(float2*)&g_V[row0 * H_DIM + hc0] =
                    make_float2(acc[mt][nt][0], acc[mt][nt][1]);
                *(float2*)&g_V[(row0 + 8) * H_DIM + hc0] =
                    make_float2(acc[mt][nt][2], acc[mt][nt][3]);
            }
        }
    }
}

// ===========================================================================
// Kernel 2: sparse attention with L1 window reuse.
// CTA = 1024 threads (32 warps), 64 consecutive nodes, grid = 128 (1/SM).
// Iteration t: warp w handles node i0 + 32t + w, so all warps march through
// the same ~450-row sliding K/V window together -> window stays L1-resident
// (448 rows x (128B bf16-K + 256B fp32-V) ~ 172KB < 228KB L1). No smem.
// ===========================================================================
__device__ __forceinline__ float qk_dot8(float4 q0, float4 q1, uint4 kd) {
    __nv_bfloat162 b;
    float2 f;
    float part;
    b = *(__nv_bfloat162*)&kd.x; f = __bfloat1622float2(b);
    part  = q0.x * f.x + q0.y * f.y;
    b = *(__nv_bfloat162*)&kd.y; f = __bfloat1622float2(b);
    part += q0.z * f.x + q0.w * f.y;
    b = *(__nv_bfloat162*)&kd.z; f = __bfloat1622float2(b);
    part += q1.x * f.x + q1.y * f.y;
    b = *(__nv_bfloat162*)&kd.w; f = __bfloat1622float2(b);
    part += q1.z * f.x + q1.w * f.y;
    return part;
}

#define ATT_BLOCK 1024
#define ATT_NPC   64

__global__ __launch_bounds__(ATT_BLOCK) void attn_kernel(
    const int*   __restrict__ edge_index,   // [2, E]: src then dst
    const int*   __restrict__ edge_type,    // [E]
    const float* __restrict__ ek_table,     // [16]
    float*       __restrict__ out)          // [N, 64]
{
    const int lane = threadIdx.x & 31;
    const int w    = threadIdx.x >> 5;       // 0..31
    const int i0   = blockIdx.x * ATT_NPC;

    #pragma unroll
    for (int t = 0; t < ATT_NPC / 32; t++) {
        const int i = i0 + t * 32 + w;
        const int e = i * DEG + lane;
        const int   j  = edge_index[E_EDGES + e];
        const float ek = ek_table[edge_type[e]];

        // lane loads Q dims (lane&7)*8 .. +7
        const float4* Qp = (const float4*)&g_Q[i * H_DIM + (lane & 7) * 8];
        const float4 q0 = Qp[0], q1 = Qp[1];

        // scores: pass covers neighbors 4p..4p+3; 8 lanes per neighbor row
        float s = 0.f;
        #pragma unroll
        for (int pass = 0; pass < 8; pass++) {
            int n  = pass * 4 + (lane >> 3);
            int jn = __shfl_sync(0xffffffffu, j, n);
            uint4 kd = *(const uint4*)&g_Kb[jn * 32 + (lane & 7) * 4];
            float part = qk_dot8(q0, q1, kd);
            part += __shfl_xor_sync(0xffffffffu, part, 1);
            part += __shfl_xor_sync(0xffffffffu, part, 2);
            part += __shfl_xor_sync(0xffffffffu, part, 4);
            float st = __shfl_sync(0xffffffffu, part, (lane & 3) * 8);
            if (pass == (lane >> 2)) s = st;
        }
        s = (s + ek) * (1.0f / 512.0f);     // (/H) then (/sqrt(H)) = /512

        // warp softmax over the 32 neighbor scores
        float m = s;
        #pragma unroll
        for (int o = 16; o > 0; o >>= 1)
            m = fmaxf(m, __shfl_xor_sync(0xffffffffu, m, o));
        const float pexp = __expf(s - m);
        float sum = pexp;
        #pragma unroll
        for (int o = 16; o > 0; o >>= 1)
            sum += __shfl_xor_sync(0xffffffffu, sum, o);
        const float p = pexp / sum;

        // weighted V sum: lane owns output dims {2*lane, 2*lane+1}
        float a0 = 0.f, a1 = 0.f;
        #pragma unroll
        for (int n = 0; n < DEG; n++) {
            const float pn = __shfl_sync(0xffffffffu, p, n);
            const int   jn = __shfl_sync(0xffffffffu, j, n);
            const float2 v = *(const float2*)&g_V[jn * H_DIM + lane * 2];
            a0 += pn * v.x;
            a1 += pn * v.y;
        }
        *(float2*)&out[i * H_DIM + lane * 2] = make_float2(a0, a1);
    }
}

// ---------------------------------------------------------------------------
extern "C" void kernel_launch(void* const* d_in, const int* in_sizes, int n_in,
                              void* d_out, int out_size)
{
    const float* x          = (const float*)d_in[0];
    // d_in[1] = adj — intentionally unused (edge list is exact)
    const int*   edge_index = (const int*)d_in[2];
    const int*   edge_type  = (const int*)d_in[3];
    const float* Wq         = (const float*)d_in[4];
    const float* bq         = (const float*)d_in[5];
    const float* Wk         = (const float*)d_in[6];
    const float* bk         = (const float*)d_in[7];
    const float* Wv         = (const float*)d_in[8];
    const float* ekt        = (const float*)d_in[9];
    float*       out        = (float*)d_out;

    static bool attr_set = false;
    if (!attr_set) {
        cudaFuncSetAttribute(qkv_mma_kernel,
                             cudaFuncAttributeMaxDynamicSharedMemorySize, QKV_SMEM);
        attr_set = true;
    }

    wconv_kernel<<<48, 256>>>(Wq, Wk, Wv);
    qkv_mma_kernel<<<N_NODES / 64, 256, QKV_SMEM>>>(x, bq, bk);
    attn_kernel<<<N_NODES / ATT_NPC, ATT_BLOCK>>>(edge_index, edge_type, ekt, out);
}

// round 9
// speedup vs baseline: 1.4517x; 1.0743x over previous
#include <cuda_runtime.h>
#include <cuda_bf16.h>
#include <cstdint>

#define N_NODES 8192
#define D_IN    256
#define H_DIM   64
#define DEG     32
#define E_EDGES (N_NODES * DEG)

// Scratch: projected Q/V (fp32), K (packed bf16 pairs)
__device__ float    g_Q[N_NODES * H_DIM];
__device__ uint32_t g_Kb[N_NODES * (H_DIM / 2)];   // bf16x2 per pair of dims
__device__ float    g_V[N_NODES * H_DIM];

// ===========================================================================
// helpers (plain sm_80-era PTX — compiles at compute_103 virtual target)
// ===========================================================================
__device__ __forceinline__ uint32_t smem_u32(const void* p) {
    uint32_t a;
    asm("{ .reg .u64 t; cvta.to.shared.u64 t, %1; cvt.u32.u64 %0, t; }"
        : "=r"(a) : "l"(p));
    return a;
}
__device__ __forceinline__ void ldmatrix_x4(uint32_t* r, uint32_t addr) {
    asm volatile("ldmatrix.sync.aligned.m8n8.x4.shared.b16 {%0,%1,%2,%3}, [%4];"
                 : "=r"(r[0]), "=r"(r[1]), "=r"(r[2]), "=r"(r[3]) : "r"(addr));
}
__device__ __forceinline__ void mma_bf16(float* c, const uint32_t* a, const uint32_t* b) {
    asm volatile(
        "mma.sync.aligned.m16n8k16.row.col.f32.bf16.bf16.f32 "
        "{%0,%1,%2,%3}, {%4,%5,%6,%7}, {%8,%9}, {%0,%1,%2,%3};"
        : "+f"(c[0]), "+f"(c[1]), "+f"(c[2]), "+f"(c[3])
        : "r"(a[0]), "r"(a[1]), "r"(a[2]), "r"(a[3]), "r"(b[0]), "r"(b[1]));
}

// split a float4 into packed bf16 hi (uint2) + lo (uint2)
__device__ __forceinline__ void split4(float4 v, uint2& hv, uint2& lv) {
    float f[4] = {v.x, v.y, v.z, v.w};
    unsigned short hu[4], lu[4];
    #pragma unroll
    for (int i = 0; i < 4; i++) {
        __nv_bfloat16 hb = __float2bfloat16(f[i]);
        __nv_bfloat16 lb = __float2bfloat16(f[i] - __bfloat162float(hb));
        hu[i] = __bfloat16_as_ushort(hb);
        lu[i] = __bfloat16_as_ushort(lb);
    }
    hv = make_uint2((uint32_t)hu[0] | ((uint32_t)hu[1] << 16),
                    (uint32_t)hu[2] | ((uint32_t)hu[3] << 16));
    lv = make_uint2((uint32_t)lu[0] | ((uint32_t)lu[1] << 16),
                    (uint32_t)lu[2] | ((uint32_t)lu[3] << 16));
}

// ===========================================================================
// Kernel 1: QKV projection, bf16-split GEMM via mma.sync (m16n8k16).
//   BOTH x and W loaded fp32 and split to bf16 hi/lo in registers — no
//   separate convert kernel. Register-pipelined K-chunks (regs hold chunk
//   it+1 during chunk it's MMA), double-buffered smem, 1 sync per chunk.
// CTA: 64 rows x 192 cols, 256 threads, warp tile 32x48, 4 K-chunks of 64.
// ===========================================================================
#define LDS_B     144               // padded row stride in bytes (72 bf16)
#define A_ONE     (64 * LDS_B)      // 9216  (one of hi/lo)
#define A_BUF     (2 * A_ONE)       // 18432 (hi + lo)
#define B_ONE     (192 * LDS_B)     // 27648
#define B_STAGE   (2 * B_ONE)       // 55296 (hi + lo)
#define B_OFF     (2 * A_BUF)       // 36864
#define QKV_SMEM  (B_OFF + 2 * B_STAGE)   // 147456

__device__ __forceinline__ void ld_a(const float* __restrict__ x,
                                     int it, int r0, int tid, float4* r) {
    const int kk = it * 64;
    #pragma unroll
    for (int t = 0; t < 4; t++) {
        int idx = tid + t * 256;       // 0..1023
        int row = idx >> 4, c4 = idx & 15;
        r[t] = *(const float4*)&x[(r0 + row) * D_IN + kk + c4 * 4];
    }
}
__device__ __forceinline__ void ld_b(const float* __restrict__ Wq,
                                     const float* __restrict__ Wk,
                                     const float* __restrict__ Wv,
                                     int it, int tid, float4* r) {
    const int kk = it * 64;
    #pragma unroll
    for (int t = 0; t < 12; t++) {
        int idx = tid + t * 256;       // 0..3071
        int row = idx >> 4, c4 = idx & 15;
        const float* src = (row < 64)  ? &Wq[row * D_IN]
                         : (row < 128) ? &Wk[(row - 64) * D_IN]
                                       : &Wv[(row - 128) * D_IN];
        r[t] = *(const float4*)&src[kk + c4 * 4];
    }
}
__device__ __forceinline__ void st_split(uint32_t hi_base, uint32_t lo_base,
                                         int idx, float4 v) {
    int row = idx >> 4, c4 = idx & 15;
    uint32_t off = (uint32_t)(row * LDS_B + c4 * 8);
    uint2 hv, lv;
    split4(v, hv, lv);
    asm volatile("st.shared.v2.b32 [%0], {%1, %2};"
                 :: "r"(hi_base + off), "r"(hv.x), "r"(hv.y) : "memory");
    asm volatile("st.shared.v2.b32 [%0], {%1, %2};"
                 :: "r"(lo_base + off), "r"(lv.x), "r"(lv.y) : "memory");
}
__device__ __forceinline__ void st_a(uint32_t abuf, int tid, const float4* r) {
    #pragma unroll
    for (int t = 0; t < 4; t++)
        st_split(abuf, abuf + A_ONE, tid + t * 256, r[t]);
}
__device__ __forceinline__ void st_b(uint32_t bbuf, int tid, const float4* r) {
    #pragma unroll
    for (int t = 0; t < 12; t++)
        st_split(bbuf, bbuf + B_ONE, tid + t * 256, r[t]);
}

__global__ __launch_bounds__(256) void qkv_mma_kernel(
    const float* __restrict__ x,
    const float* __restrict__ Wq, const float* __restrict__ bq,
    const float* __restrict__ Wk, const float* __restrict__ bk,
    const float* __restrict__ Wv)
{
    extern __shared__ __align__(16) char sm[];
    const int tid  = threadIdx.x;
    const int lane = tid & 31;
    const int wid  = tid >> 5;
    const int wm   = wid & 1;       // 2 M sub-tiles of 32
    const int wn   = wid >> 1;      // 4 N sub-tiles of 48
    const int r0   = blockIdx.x * 64;
    const uint32_t sbase = smem_u32(sm);

    float acc[2][6][4];
    #pragma unroll
    for (int mt = 0; mt < 2; mt++)
        #pragma unroll
        for (int nt = 0; nt < 6; nt++)
            #pragma unroll
            for (int q = 0; q < 4; q++) acc[mt][nt][q] = 0.f;

    float4 ra[4], rb[12];
    // prologue: chunk 0 -> buf0; chunk 1 held in regs
    ld_a(x, 0, r0, tid, ra);
    ld_b(Wq, Wk, Wv, 0, tid, rb);
    st_a(sbase, tid, ra);
    st_b(sbase + B_OFF, tid, rb);
    ld_a(x, 1, r0, tid, ra);
    ld_b(Wq, Wk, Wv, 1, tid, rb);
    __syncthreads();

    #pragma unroll 1
    for (int it = 0; it < 4; it++) {
        // store chunk it+1 (held in regs) to the other buffer
        if (it < 3) {
            uint32_t nb = (uint32_t)((it + 1) & 1);
            st_a(sbase + nb * A_BUF, tid, ra);
            st_b(sbase + B_OFF + nb * B_STAGE, tid, rb);
        }

        const uint32_t sa_h = sbase + (uint32_t)(it & 1) * A_BUF;
        const uint32_t sa_l = sa_h + A_ONE;
        const uint32_t sb_h = sbase + B_OFF + (uint32_t)(it & 1) * B_STAGE;
        const uint32_t sb_l = sb_h + B_ONE;

        #pragma unroll
        for (int ks = 0; ks < 4; ks++) {
            const int kb = ks * 16;
            const uint32_t acol = (uint32_t)((kb + (lane >> 4) * 8) * 2);
            uint32_t ah[2][4], al[2][4];
            #pragma unroll
            for (int mt = 0; mt < 2; mt++) {
                int row = wm * 32 + mt * 16 + (lane & 15);
                ldmatrix_x4(ah[mt], sa_h + row * LDS_B + acol);
                ldmatrix_x4(al[mt], sa_l + row * LDS_B + acol);
            }
            uint32_t bh[6][2], bl[6][2];
            const uint32_t bcol = (uint32_t)((kb + ((lane >> 3) & 1) * 8) * 2);
            #pragma unroll
            for (int np = 0; np < 3; np++) {
                int row = wn * 48 + np * 16 + (lane >> 4) * 8 + (lane & 7);
                uint32_t r[4];
                ldmatrix_x4(r, sb_h + row * LDS_B + bcol);
                bh[np * 2][0] = r[0]; bh[np * 2][1] = r[1];
                bh[np * 2 + 1][0] = r[2]; bh[np * 2 + 1][1] = r[3];
                ldmatrix_x4(r, sb_l + row * LDS_B + bcol);
                bl[np * 2][0] = r[0]; bl[np * 2][1] = r[1];
                bl[np * 2 + 1][0] = r[2]; bl[np * 2 + 1][1] = r[3];
            }
            #pragma unroll
            for (int mt = 0; mt < 2; mt++)
                #pragma unroll
                for (int nt = 0; nt < 6; nt++) {
                    mma_bf16(acc[mt][nt], ah[mt], bh[nt]);
                    mma_bf16(acc[mt][nt], ah[mt], bl[nt]);
                    mma_bf16(acc[mt][nt], al[mt], bh[nt]);
                }
        }

        // fetch chunk it+2 into regs (overlaps MMA tail)
        if (it < 2) {
            ld_a(x, it + 2, r0, tid, ra);
            ld_b(Wq, Wk, Wv, it + 2, tid, rb);
        }
        __syncthreads();
    }

    // epilogue: fragments -> g_Q (fp32+bias) / g_Kb (bf16 pairs+bias) / g_V
    const int grp = lane >> 2;
    const int qid = lane & 3;
    #pragma unroll
    for (int mt = 0; mt < 2; mt++) {
        int row0 = r0 + wm * 32 + mt * 16 + grp;
        #pragma unroll
        for (int nt = 0; nt < 6; nt++) {
            int cb  = wn * 48 + nt * 8;
            int h   = cb >> 6;
            int hc0 = (cb & 63) + qid * 2;
            if (h == 0) {
                float b0 = bq[hc0], b1 = bq[hc0 + 1];
                *(float2*)&g_Q[row0 * H_DIM + hc0] =
                    make_float2(acc[mt][nt][0] + b0, acc[mt][nt][1] + b1);
                *(float2*)&g_Q[(row0 + 8) * H_DIM + hc0] =
                    make_float2(acc[mt][nt][2] + b0, acc[mt][nt][3] + b1);
            } else if (h == 1) {
                float b0 = bk[hc0], b1 = bk[hc0 + 1];
                int pr = hc0 >> 1;
                __nv_bfloat162 k0 = __floats2bfloat162_rn(acc[mt][nt][0] + b0,
                                                          acc[mt][nt][1] + b1);
                __nv_bfloat162 k1 = __floats2bfloat162_rn(acc[mt][nt][2] + b0,
                                                          acc[mt][nt][3] + b1);
                g_Kb[row0 * 32 + pr]       = *(uint32_t*)&k0;
                g_Kb[(row0 + 8) * 32 + pr] = *(uint32_t*)&k1;
            } else {
                *(float2*)&g_V[row0 * H_DIM + hc0] =
                    make_float2(acc[mt][nt][0], acc[mt][nt][1]);
                *(float2*)&g_V[(row0 + 8) * H_DIM + hc0] =
                    make_float2(acc[mt][nt][2], acc[mt][nt][3]);
            }
        }
    }
}

// ===========================================================================
// Kernel 2: sparse attention with L1 window reuse.
// CTA = 896 threads (28 warps), 56 consecutive nodes, grid = 147 (~1/SM).
// All warps march through the same ~470-row sliding K/V window together ->
// window stays L1-resident (~180KB < 228KB L1). No smem.
// ===========================================================================
__device__ __forceinline__ float qk_dot8(float4 q0, float4 q1, uint4 kd) {
    __nv_bfloat162 b;
    float2 f;
    float part;
    b = *(__nv_bfloat162*)&kd.x; f = __bfloat1622float2(b);
    part  = q0.x * f.x + q0.y * f.y;
    b = *(__nv_bfloat162*)&kd.y; f = __bfloat1622float2(b);
    part += q0.z * f.x + q0.w * f.y;
    b = *(__nv_bfloat162*)&kd.z; f = __bfloat1622float2(b);
    part += q1.x * f.x + q1.y * f.y;
    b = *(__nv_bfloat162*)&kd.w; f = __bfloat1622float2(b);
    part += q1.z * f.x + q1.w * f.y;
    return part;
}

#define ATT_WPB   28
#define ATT_NPC   56
#define ATT_GRID  ((N_NODES + ATT_NPC - 1) / ATT_NPC)

__global__ __launch_bounds__(ATT_WPB * 32) void attn_kernel(
    const int*   __restrict__ edge_index,   // [2, E]: src then dst
    const int*   __restrict__ edge_type,    // [E]
    const float* __restrict__ ek_table,     // [16]
    float*       __restrict__ out)          // [N, 64]
{
    const int lane = threadIdx.x & 31;
    const int w    = threadIdx.x >> 5;       // 0..27
    const int i0   = blockIdx.x * ATT_NPC;

    #pragma unroll
    for (int t = 0; t < 2; t++) {
        const int i = i0 + t * ATT_WPB + w;
        if (i >= N_NODES) break;              // warp-uniform guard
        const int e = i * DEG + lane;
        const int   j  = edge_index[E_EDGES + e];
        const float ek = ek_table[edge_type[e]];

        // lane loads Q dims (lane&7)*8 .. +7
        const float4* Qp = (const float4*)&g_Q[i * H_DIM + (lane & 7) * 8];
        const float4 q0 = Qp[0], q1 = Qp[1];

        // scores: pass covers neighbors 4p..4p+3; 8 lanes per neighbor row
        float s = 0.f;
        #pragma unroll
        for (int pass = 0; pass < 8; pass++) {
            int n  = pass * 4 + (lane >> 3);
            int jn = __shfl_sync(0xffffffffu, j, n);
            uint4 kd = *(const uint4*)&g_Kb[jn * 32 + (lane & 7) * 4];
            float part = qk_dot8(q0, q1, kd);
            part += __shfl_xor_sync(0xffffffffu, part, 1);
            part += __shfl_xor_sync(0xffffffffu, part, 2);
            part += __shfl_xor_sync(0xffffffffu, part, 4);
            float st = __shfl_sync(0xffffffffu, part, (lane & 3) * 8);
            if (pass == (lane >> 2)) s = st;
        }
        s = (s + ek) * (1.0f / 512.0f);     // (/H) then (/sqrt(H)) = /512

        // warp softmax over the 32 neighbor scores
        float m = s;
        #pragma unroll
        for (int o = 16; o > 0; o >>= 1)
            m = fmaxf(m, __shfl_xor_sync(0xffffffffu, m, o));
        const float pexp = __expf(s - m);
        float sum = pexp;
        #pragma unroll
        for (int o = 16; o > 0; o >>= 1)
            sum += __shfl_xor_sync(0xffffffffu, sum, o);
        const float p = pexp / sum;

        // weighted V sum: lane owns output dims {2*lane, 2*lane+1}
        float a0 = 0.f, a1 = 0.f;
        #pragma unroll
        for (int n = 0; n < DEG; n++) {
            const float pn = __shfl_sync(0xffffffffu, p, n);
            const int   jn = __shfl_sync(0xffffffffu, j, n);
            const float2 v = *(const float2*)&g_V[jn * H_DIM + lane * 2];
            a0 += pn * v.x;
            a1 += pn * v.y;
        }
        *(float2*)&out[i * H_DIM + lane * 2] = make_float2(a0, a1);
    }
}

// ---------------------------------------------------------------------------
extern "C" void kernel_launch(void* const* d_in, const int* in_sizes, int n_in,
                              void* d_out, int out_size)
{
    const float* x          = (const float*)d_in[0];
    // d_in[1] = adj — intentionally unused (edge list is exact)
    const int*   edge_index = (const int*)d_in[2];
    const int*   edge_type  = (const int*)d_in[3];
    const float* Wq         = (const float*)d_in[4];
    const float* bq         = (const float*)d_in[5];
    const float* Wk         = (const float*)d_in[6];
    const float* bk         = (const float*)d_in[7];
    const float* Wv         = (const float*)d_in[8];
    const float* ekt        = (const float*)d_in[9];
    float*       out        = (float*)d_out;

    static bool attr_set = false;
    if (!attr_set) {
        cudaFuncSetAttribute(qkv_mma_kernel,
                             cudaFuncAttributeMaxDynamicSharedMemorySize, QKV_SMEM);
        attr_set = true;
    }

    qkv_mma_kernel<<<N_NODES / 64, 256, QKV_SMEM>>>(x, Wq, bq, Wk, bk, Wv);
    attn_kernel<<<ATT_GRID, ATT_WPB * 32>>>(edge_index, edge_type, ekt, out);
}

// round 10
// speedup vs baseline: 1.7338x; 1.1944x over previous
#include <cuda_runtime.h>
#include <cuda_bf16.h>
#include <cuda_fp16.h>
#include <cstdint>

#define N_NODES 8192
#define D_IN    256
#define H_DIM   64
#define DEG     32
#define E_EDGES (N_NODES * DEG)

// Scratch: projected Q/V (fp32), K (packed bf16 pairs)
__device__ float    g_Q[N_NODES * H_DIM];
__device__ uint32_t g_Kb[N_NODES * (H_DIM / 2)];   // bf16x2 per pair of dims
__device__ float    g_V[N_NODES * H_DIM];

// ===========================================================================
// helpers (plain sm_80-era PTX — compiles at compute_103 virtual target)
// ===========================================================================
__device__ __forceinline__ uint32_t smem_u32(const void* p) {
    uint32_t a;
    asm("{ .reg .u64 t; cvta.to.shared.u64 t, %1; cvt.u32.u64 %0, t; }"
        : "=r"(a) : "l"(p));
    return a;
}
__device__ __forceinline__ void ldmatrix_x4(uint32_t* r, uint32_t addr) {
    asm volatile("ldmatrix.sync.aligned.m8n8.x4.shared.b16 {%0,%1,%2,%3}, [%4];"
                 : "=r"(r[0]), "=r"(r[1]), "=r"(r[2]), "=r"(r[3]) : "r"(addr));
}
__device__ __forceinline__ void mma_f16(float* c, const uint32_t* a, const uint32_t* b) {
    asm volatile(
        "mma.sync.aligned.m16n8k16.row.col.f32.f16.f16.f32 "
        "{%0,%1,%2,%3}, {%4,%5,%6,%7}, {%8,%9}, {%0,%1,%2,%3};"
        : "+f"(c[0]), "+f"(c[1]), "+f"(c[2]), "+f"(c[3])
        : "r"(a[0]), "r"(a[1]), "r"(a[2]), "r"(a[3]), "r"(b[0]), "r"(b[1]));
}

// split a float4 into packed fp16 hi (uint2) + lo (uint2); hi+lo ~ 22-bit exact
__device__ __forceinline__ void split4_f16(float4 v, uint2& hv, uint2& lv) {
    float f[4] = {v.x, v.y, v.z, v.w};
    __half h[4], l[4];
    #pragma unroll
    for (int i = 0; i < 4; i++) {
        h[i] = __float2half_rn(f[i]);
        l[i] = __float2half_rn(f[i] - __half2float(h[i]));
    }
    __half2 h01 = __halves2half2(h[0], h[1]);
    __half2 h23 = __halves2half2(h[2], h[3]);
    __half2 l01 = __halves2half2(l[0], l[1]);
    __half2 l23 = __halves2half2(l[2], l[3]);
    hv = make_uint2(*(uint32_t*)&h01, *(uint32_t*)&h23);
    lv = make_uint2(*(uint32_t*)&l01, *(uint32_t*)&l23);
}
// plain fp16 convert of a float4 -> uint2
__device__ __forceinline__ uint2 cvt4_f16(float4 v) {
    __half2 a = __floats2half2_rn(v.x, v.y);
    __half2 b = __floats2half2_rn(v.z, v.w);
    return make_uint2(*(uint32_t*)&a, *(uint32_t*)&b);
}

// ===========================================================================
// Kernel 1: QKV projection via fp16 mma.sync (m16n8k16), 2-term split:
//   D = Ah*B + Al*B  (A = x split to fp16 hi/lo — exact; B = fp16(W)).
//   Error = W's fp16 rounding only (~2.4e-4 element), fp32 accumulate.
// CTA: 64 rows x 192 cols, 256 threads, warp tile 32x48, 4 K-chunks of 64.
// Register-pipelined chunks, double-buffered smem, no convert pre-kernel.
// ===========================================================================
#define LDS_B     144               // padded row stride in bytes (72 fp16)
#define A_ONE     (64 * LDS_B)      // 9216  (one of hi/lo)
#define A_BUF     (2 * A_ONE)       // 18432 (hi + lo)
#define B_ONE     (192 * LDS_B)     // 27648 (single fp16)
#define B_OFF     (2 * A_BUF)       // 36864
#define QKV_SMEM  (B_OFF + 2 * B_ONE)   // 92160

__device__ __forceinline__ void ld_a(const float* __restrict__ x,
                                     int it, int r0, int tid, float4* r) {
    const int kk = it * 64;
    #pragma unroll
    for (int t = 0; t < 4; t++) {
        int idx = tid + t * 256;       // 0..1023
        int row = idx >> 4, c4 = idx & 15;
        r[t] = *(const float4*)&x[(r0 + row) * D_IN + kk + c4 * 4];
    }
}
__device__ __forceinline__ void ld_b(const float* __restrict__ Wq,
                                     const float* __restrict__ Wk,
                                     const float* __restrict__ Wv,
                                     int it, int tid, float4* r) {
    const int kk = it * 64;
    #pragma unroll
    for (int t = 0; t < 12; t++) {
        int idx = tid + t * 256;       // 0..3071
        int row = idx >> 4, c4 = idx & 15;
        const float* src = (row < 64)  ? &Wq[row * D_IN]
                         : (row < 128) ? &Wk[(row - 64) * D_IN]
                                       : &Wv[(row - 128) * D_IN];
        r[t] = *(const float4*)&src[kk + c4 * 4];
    }
}
__device__ __forceinline__ void st_a(uint32_t abuf, int tid, const float4* r) {
    #pragma unroll
    for (int t = 0; t < 4; t++) {
        int idx = tid + t * 256;
        int row = idx >> 4, c4 = idx & 15;
        uint32_t off = (uint32_t)(row * LDS_B + c4 * 8);
        uint2 hv, lv;
        split4_f16(r[t], hv, lv);
        asm volatile("st.shared.v2.b32 [%0], {%1, %2};"
                     :: "r"(abuf + off), "r"(hv.x), "r"(hv.y) : "memory");
        asm volatile("st.shared.v2.b32 [%0], {%1, %2};"
                     :: "r"(abuf + A_ONE + off), "r"(lv.x), "r"(lv.y) : "memory");
    }
}
__device__ __forceinline__ void st_b(uint32_t bbuf, int tid, const float4* r) {
    #pragma unroll
    for (int t = 0; t < 12; t++) {
        int idx = tid + t * 256;
        int row = idx >> 4, c4 = idx & 15;
        uint32_t off = (uint32_t)(row * LDS_B + c4 * 8);
        uint2 hv = cvt4_f16(r[t]);
        asm volatile("st.shared.v2.b32 [%0], {%1, %2};"
                     :: "r"(bbuf + off), "r"(hv.x), "r"(hv.y) : "memory");
    }
}

__global__ __launch_bounds__(256) void qkv_mma_kernel(
    const float* __restrict__ x,
    const float* __restrict__ Wq, const float* __restrict__ bq,
    const float* __restrict__ Wk, const float* __restrict__ bk,
    const float* __restrict__ Wv)
{
    extern __shared__ __align__(16) char sm[];
    const int tid  = threadIdx.x;
    const int lane = tid & 31;
    const int wid  = tid >> 5;
    const int wm   = wid & 1;       // 2 M sub-tiles of 32
    const int wn   = wid >> 1;      // 4 N sub-tiles of 48
    const int r0   = blockIdx.x * 64;
    const uint32_t sbase = smem_u32(sm);

    float acc[2][6][4];
    #pragma unroll
    for (int mt = 0; mt < 2; mt++)
        #pragma unroll
        for (int nt = 0; nt < 6; nt++)
            #pragma unroll
            for (int q = 0; q < 4; q++) acc[mt][nt][q] = 0.f;

    float4 ra[4], rb[12];
    // prologue: chunk 0 -> buf0; chunk 1 held in regs
    ld_a(x, 0, r0, tid, ra);
    ld_b(Wq, Wk, Wv, 0, tid, rb);
    st_a(sbase, tid, ra);
    st_b(sbase + B_OFF, tid, rb);
    ld_a(x, 1, r0, tid, ra);
    ld_b(Wq, Wk, Wv, 1, tid, rb);
    __syncthreads();

    #pragma unroll 1
    for (int it = 0; it < 4; it++) {
        // store chunk it+1 (held in regs) to the other buffer
        if (it < 3) {
            uint32_t nb = (uint32_t)((it + 1) & 1);
            st_a(sbase + nb * A_BUF, tid, ra);
            st_b(sbase + B_OFF + nb * B_ONE, tid, rb);
        }

        const uint32_t sa_h = sbase + (uint32_t)(it & 1) * A_BUF;
        const uint32_t sa_l = sa_h + A_ONE;
        const uint32_t sb   = sbase + B_OFF + (uint32_t)(it & 1) * B_ONE;

        #pragma unroll
        for (int ks = 0; ks < 4; ks++) {
            const int kb = ks * 16;
            const uint32_t acol = (uint32_t)((kb + (lane >> 4) * 8) * 2);
            uint32_t ah[2][4], al[2][4];
            #pragma unroll
            for (int mt = 0; mt < 2; mt++) {
                int row = wm * 32 + mt * 16 + (lane & 15);
                ldmatrix_x4(ah[mt], sa_h + row * LDS_B + acol);
                ldmatrix_x4(al[mt], sa_l + row * LDS_B + acol);
            }
            uint32_t bf[6][2];
            const uint32_t bcol = (uint32_t)((kb + ((lane >> 3) & 1) * 8) * 2);
            #pragma unroll
            for (int np = 0; np < 3; np++) {
                int row = wn * 48 + np * 16 + (lane >> 4) * 8 + (lane & 7);
                uint32_t r[4];
                ldmatrix_x4(r, sb + row * LDS_B + bcol);
                bf[np * 2][0] = r[0]; bf[np * 2][1] = r[1];
                bf[np * 2 + 1][0] = r[2]; bf[np * 2 + 1][1] = r[3];
            }
            #pragma unroll
            for (int mt = 0; mt < 2; mt++)
                #pragma unroll
                for (int nt = 0; nt < 6; nt++) {
                    mma_f16(acc[mt][nt], ah[mt], bf[nt]);
                    mma_f16(acc[mt][nt], al[mt], bf[nt]);
                }
        }

        // fetch chunk it+2 into regs (overlaps MMA tail)
        if (it < 2) {
            ld_a(x, it + 2, r0, tid, ra);
            ld_b(Wq, Wk, Wv, it + 2, tid, rb);
        }
        __syncthreads();
    }

    // epilogue: fragments -> g_Q (fp32+bias) / g_Kb (bf16 pairs+bias) / g_V
    const int grp = lane >> 2;
    const int qid = lane & 3;
    #pragma unroll
    for (int mt = 0; mt < 2; mt++) {
        int row0 = r0 + wm * 32 + mt * 16 + grp;
        #pragma unroll
        for (int nt = 0; nt < 6; nt++) {
            int cb  = wn * 48 + nt * 8;
            int h   = cb >> 6;
            int hc0 = (cb & 63) + qid * 2;
            if (h == 0) {
                float b0 = bq[hc0], b1 = bq[hc0 + 1];
                *(float2*)&g_Q[row0 * H_DIM + hc0] =
                    make_float2(acc[mt][nt][0] + b0, acc[mt][nt][1] + b1);
                *(float2*)&g_Q[(row0 + 8) * H_DIM + hc0] =
                    make_float2(acc[mt][nt][2] + b0, acc[mt][nt][3] + b1);
            } else if (h == 1) {
                float b0 = bk[hc0], b1 = bk[hc0 + 1];
                int pr = hc0 >> 1;
                __nv_bfloat162 k0 = __floats2bfloat162_rn(acc[mt][nt][0] + b0,
                                                          acc[mt][nt][1] + b1);
                __nv_bfloat162 k1 = __floats2bfloat162_rn(acc[mt][nt][2] + b0,
                                                          acc[mt][nt][3] + b1);
                g_Kb[row0 * 32 + pr]       = *(uint32_t*)&k0;
                g_Kb[(row0 + 8) * 32 + pr] = *(uint32_t*)&k1;
            } else {
                *(float2*)&g_V[row0 * H_DIM + hc0] =
                    make_float2(acc[mt][nt][0], acc[mt][nt][1]);
                *(float2*)&g_V[(row0 + 8) * H_DIM + hc0] =
                    make_float2(acc[mt][nt][2], acc[mt][nt][3]);
            }
        }
    }
}

// ===========================================================================
// Kernel 2: sparse attention with L1 window reuse.
// CTA = 896 threads (28 warps), 56 consecutive nodes, grid = 147 (~1/SM).
// V loop restructured: half-warps process even/odd neighbors in parallel,
// lane owns 4 output dims, float4 gathers, xor-16 combine at the end.
// ===========================================================================
__device__ __forceinline__ float qk_dot8(float4 q0, float4 q1, uint4 kd) {
    __nv_bfloat162 b;
    float2 f;
    float part;
    b = *(__nv_bfloat162*)&kd.x; f = __bfloat1622float2(b);
    part  = q0.x * f.x + q0.y * f.y;
    b = *(__nv_bfloat162*)&kd.y; f = __bfloat1622float2(b);
    part += q0.z * f.x + q0.w * f.y;
    b = *(__nv_bfloat162*)&kd.z; f = __bfloat1622float2(b);
    part += q1.x * f.x + q1.y * f.y;
    b = *(__nv_bfloat162*)&kd.w; f = __bfloat1622float2(b);
    part += q1.z * f.x + q1.w * f.y;
    return part;
}

#define ATT_WPB   28
#define ATT_NPC   56
#define ATT_GRID  ((N_NODES + ATT_NPC - 1) / ATT_NPC)

__global__ __launch_bounds__(ATT_WPB * 32) void attn_kernel(
    const int*   __restrict__ edge_index,   // [2, E]: src then dst
    const int*   __restrict__ edge_type,    // [E]
    const float* __restrict__ ek_table,     // [16]
    float*       __restrict__ out)          // [N, 64]
{
    const int lane = threadIdx.x & 31;
    const int w    = threadIdx.x >> 5;       // 0..27
    const int i0   = blockIdx.x * ATT_NPC;

    #pragma unroll
    for (int t = 0; t < 2; t++) {
        const int i = i0 + t * ATT_WPB + w;
        if (i >= N_NODES) break;              // warp-uniform guard
        const int e = i * DEG + lane;
        const int   j  = edge_index[E_EDGES + e];
        const float ek = ek_table[edge_type[e]];

        // lane loads Q dims (lane&7)*8 .. +7
        const float4* Qp = (const float4*)&g_Q[i * H_DIM + (lane & 7) * 8];
        const float4 q0 = Qp[0], q1 = Qp[1];

        // scores: pass covers neighbors 4p..4p+3; 8 lanes per neighbor row
        float s = 0.f;
        #pragma unroll
        for (int pass = 0; pass < 8; pass++) {
            int n  = pass * 4 + (lane >> 3);
            int jn = __shfl_sync(0xffffffffu, j, n);
            uint4 kd = *(const uint4*)&g_Kb[jn * 32 + (lane & 7) * 4];
            float part = qk_dot8(q0, q1, kd);
            part += __shfl_xor_sync(0xffffffffu, part, 1);
            part += __shfl_xor_sync(0xffffffffu, part, 2);
            part += __shfl_xor_sync(0xffffffffu, part, 4);
            float st = __shfl_sync(0xffffffffu, part, (lane & 3) * 8);
            if (pass == (lane >> 2)) s = st;
        }
        s = (s + ek) * (1.0f / 512.0f);     // (/H) then (/sqrt(H)) = /512

        // warp softmax over the 32 neighbor scores
        float m = s;
        #pragma unroll
        for (int o = 16; o > 0; o >>= 1)
            m = fmaxf(m, __shfl_xor_sync(0xffffffffu, m, o));
        const float pexp = __expf(s - m);
        float sum = pexp;
        #pragma unroll
        for (int o = 16; o > 0; o >>= 1)
            sum += __shfl_xor_sync(0xffffffffu, sum, o);
        const float p = pexp / sum;

        // weighted V sum: lane owns dims 4c..4c+3 (c = lane&15);
        // half-warp g = lane>>4 processes neighbors 2t+g.
        const int c = lane & 15;
        const int g = lane >> 4;
        float4 a4 = make_float4(0.f, 0.f, 0.f, 0.f);
        #pragma unroll
        for (int n2 = 0; n2 < 16; n2++) {
            const int   n  = 2 * n2 + g;
            const float pn = __shfl_sync(0xffffffffu, p, n);
            const int   jn = __shfl_sync(0xffffffffu, j, n);
            const float4 v = *(const float4*)&g_V[jn * H_DIM + c * 4];
            a4.x += pn * v.x;
            a4.y += pn * v.y;
            a4.z += pn * v.z;
            a4.w += pn * v.w;
        }
        a4.x += __shfl_xor_sync(0xffffffffu, a4.x, 16);
        a4.y += __shfl_xor_sync(0xffffffffu, a4.y, 16);
        a4.z += __shfl_xor_sync(0xffffffffu, a4.z, 16);
        a4.w += __shfl_xor_sync(0xffffffffu, a4.w, 16);
        if (g == 0)
            *(float4*)&out[i * H_DIM + c * 4] = a4;
    }
}

// ---------------------------------------------------------------------------
extern "C" void kernel_launch(void* const* d_in, const int* in_sizes, int n_in,
                              void* d_out, int out_size)
{
    const float* x          = (const float*)d_in[0];
    // d_in[1] = adj — intentionally unused (edge list is exact)
    const int*   edge_index = (const int*)d_in[2];
    const int*   edge_type  = (const int*)d_in[3];
    const float* Wq         = (const float*)d_in[4];
    const float* bq         = (const float*)d_in[5];
    const float* Wk         = (const float*)d_in[6];
    const float* bk         = (const float*)d_in[7];
    const float* Wv         = (const float*)d_in[8];
    const float* ekt        = (const float*)d_in[9];
    float*       out        = (float*)d_out;

    static bool attr_set = false;
    if (!attr_set) {
        cudaFuncSetAttribute(qkv_mma_kernel,
                             cudaFuncAttributeMaxDynamicSharedMemorySize, QKV_SMEM);
        attr_set = true;
    }

    qkv_mma_kernel<<<N_NODES / 64, 256, QKV_SMEM>>>(x, Wq, bq, Wk, bk, Wv);
    attn_kernel<<<ATT_GRID, ATT_WPB * 32>>>(edge_index, edge_type, ekt, out);
}

// round 11
// speedup vs baseline: 1.7738x; 1.0231x over previous
#include <cuda_runtime.h>
#include <cuda_bf16.h>
#include <cuda_fp16.h>
#include <cstdint>

#define N_NODES 8192
#define D_IN    256
#define H_DIM   64
#define DEG     32
#define E_EDGES (N_NODES * DEG)

// Scratch: projected Q/V (fp32), K (packed bf16 pairs)
__device__ float    g_Q[N_NODES * H_DIM];
__device__ uint32_t g_Kb[N_NODES * (H_DIM / 2)];   // bf16x2 per pair of dims
__device__ float    g_V[N_NODES * H_DIM];

// ===========================================================================
// helpers (plain sm_80-era PTX — compiles at compute_103 virtual target)
// ===========================================================================
__device__ __forceinline__ uint32_t smem_u32(const void* p) {
    uint32_t a;
    asm("{ .reg .u64 t; cvta.to.shared.u64 t, %1; cvt.u32.u64 %0, t; }"
        : "=r"(a) : "l"(p));
    return a;
}
__device__ __forceinline__ void ldmatrix_x4(uint32_t* r, uint32_t addr) {
    asm volatile("ldmatrix.sync.aligned.m8n8.x4.shared.b16 {%0,%1,%2,%3}, [%4];"
                 : "=r"(r[0]), "=r"(r[1]), "=r"(r[2]), "=r"(r[3]) : "r"(addr));
}
__device__ __forceinline__ void mma_f16(float* c, const uint32_t* a, const uint32_t* b) {
    asm volatile(
        "mma.sync.aligned.m16n8k16.row.col.f32.f16.f16.f32 "
        "{%0,%1,%2,%3}, {%4,%5,%6,%7}, {%8,%9}, {%0,%1,%2,%3};"
        : "+f"(c[0]), "+f"(c[1]), "+f"(c[2]), "+f"(c[3])
        : "r"(a[0]), "r"(a[1]), "r"(a[2]), "r"(a[3]), "r"(b[0]), "r"(b[1]));
}
// plain fp16 convert of a float4 -> uint2
__device__ __forceinline__ uint2 cvt4_f16(float4 v) {
    __half2 a = __floats2half2_rn(v.x, v.y);
    __half2 b = __floats2half2_rn(v.z, v.w);
    return make_uint2(*(uint32_t*)&a, *(uint32_t*)&b);
}

// ===========================================================================
// Kernel 1: QKV projection via single-pass fp16 mma.sync (m16n8k16).
//   D = fp16(x) @ fp16(W)^T, fp32 accumulate. Error ~3e-4 rel (gate: 1e-3).
// CTA: 64 rows x 192 cols, 256 threads, warp tile 32x48, 4 K-chunks of 64.
// Register-pipelined chunks, double-buffered smem, in-register converts.
// ===========================================================================
#define LDS_B     144               // padded row stride in bytes (72 fp16)
#define A_ONE     (64 * LDS_B)      // 9216
#define B_ONE     (192 * LDS_B)     // 27648
#define B_OFF     (2 * A_ONE)       // 18432
#define QKV_SMEM  (B_OFF + 2 * B_ONE)   // 73728

__device__ __forceinline__ void ld_a(const float* __restrict__ x,
                                     int it, int r0, int tid, float4* r) {
    const int kk = it * 64;
    #pragma unroll
    for (int t = 0; t < 4; t++) {
        int idx = tid + t * 256;       // 0..1023
        int row = idx >> 4, c4 = idx & 15;
        r[t] = *(const float4*)&x[(r0 + row) * D_IN + kk + c4 * 4];
    }
}
__device__ __forceinline__ void ld_b(const float* __restrict__ Wq,
                                     const float* __restrict__ Wk,
                                     const float* __restrict__ Wv,
                                     int it, int tid, float4* r) {
    const int kk = it * 64;
    #pragma unroll
    for (int t = 0; t < 12; t++) {
        int idx = tid + t * 256;       // 0..3071
        int row = idx >> 4, c4 = idx & 15;
        const float* src = (row < 64)  ? &Wq[row * D_IN]
                         : (row < 128) ? &Wk[(row - 64) * D_IN]
                                       : &Wv[(row - 128) * D_IN];
        r[t] = *(const float4*)&src[kk + c4 * 4];
    }
}
__device__ __forceinline__ void st_a(uint32_t abuf, int tid, const float4* r) {
    #pragma unroll
    for (int t = 0; t < 4; t++) {
        int idx = tid + t * 256;
        int row = idx >> 4, c4 = idx & 15;
        uint32_t off = (uint32_t)(row * LDS_B + c4 * 8);
        uint2 hv = cvt4_f16(r[t]);
        asm volatile("st.shared.v2.b32 [%0], {%1, %2};"
                     :: "r"(abuf + off), "r"(hv.x), "r"(hv.y) : "memory");
    }
}
__device__ __forceinline__ void st_b(uint32_t bbuf, int tid, const float4* r) {
    #pragma unroll
    for (int t = 0; t < 12; t++) {
        int idx = tid + t * 256;
        int row = idx >> 4, c4 = idx & 15;
        uint32_t off = (uint32_t)(row * LDS_B + c4 * 8);
        uint2 hv = cvt4_f16(r[t]);
        asm volatile("st.shared.v2.b32 [%0], {%1, %2};"
                     :: "r"(bbuf + off), "r"(hv.x), "r"(hv.y) : "memory");
    }
}

__global__ __launch_bounds__(256) void qkv_mma_kernel(
    const float* __restrict__ x,
    const float* __restrict__ Wq, const float* __restrict__ bq,
    const float* __restrict__ Wk, const float* __restrict__ bk,
    const float* __restrict__ Wv)
{
    extern __shared__ __align__(16) char sm[];
    const int tid  = threadIdx.x;
    const int lane = tid & 31;
    const int wid  = tid >> 5;
    const int wm   = wid & 1;       // 2 M sub-tiles of 32
    const int wn   = wid >> 1;      // 4 N sub-tiles of 48
    const int r0   = blockIdx.x * 64;
    const uint32_t sbase = smem_u32(sm);

    float acc[2][6][4];
    #pragma unroll
    for (int mt = 0; mt < 2; mt++)
        #pragma unroll
        for (int nt = 0; nt < 6; nt++)
            #pragma unroll
            for (int q = 0; q < 4; q++) acc[mt][nt][q] = 0.f;

    float4 ra[4], rb[12];
    // prologue: chunk 0 -> buf0; chunk 1 held in regs
    ld_a(x, 0, r0, tid, ra);
    ld_b(Wq, Wk, Wv, 0, tid, rb);
    st_a(sbase, tid, ra);
    st_b(sbase + B_OFF, tid, rb);
    ld_a(x, 1, r0, tid, ra);
    ld_b(Wq, Wk, Wv, 1, tid, rb);
    __syncthreads();

    #pragma unroll 1
    for (int it = 0; it < 4; it++) {
        // store chunk it+1 (held in regs) to the other buffer
        if (it < 3) {
            uint32_t nb = (uint32_t)((it + 1) & 1);
            st_a(sbase + nb * A_ONE, tid, ra);
            st_b(sbase + B_OFF + nb * B_ONE, tid, rb);
        }

        const uint32_t sa = sbase + (uint32_t)(it & 1) * A_ONE;
        const uint32_t sb = sbase + B_OFF + (uint32_t)(it & 1) * B_ONE;

        #pragma unroll
        for (int ks = 0; ks < 4; ks++) {
            const int kb = ks * 16;
            const uint32_t acol = (uint32_t)((kb + (lane >> 4) * 8) * 2);
            uint32_t af[2][4];
            #pragma unroll
            for (int mt = 0; mt < 2; mt++) {
                int row = wm * 32 + mt * 16 + (lane & 15);
                ldmatrix_x4(af[mt], sa + row * LDS_B + acol);
            }
            uint32_t bf[6][2];
            const uint32_t bcol = (uint32_t)((kb + ((lane >> 3) & 1) * 8) * 2);
            #pragma unroll
            for (int np = 0; np < 3; np++) {
                int row = wn * 48 + np * 16 + (lane >> 4) * 8 + (lane & 7);
                uint32_t r[4];
                ldmatrix_x4(r, sb + row * LDS_B + bcol);
                bf[np * 2][0] = r[0]; bf[np * 2][1] = r[1];
                bf[np * 2 + 1][0] = r[2]; bf[np * 2 + 1][1] = r[3];
            }
            #pragma unroll
            for (int mt = 0; mt < 2; mt++)
                #pragma unroll
                for (int nt = 0; nt < 6; nt++)
                    mma_f16(acc[mt][nt], af[mt], bf[nt]);
        }

        // fetch chunk it+2 into regs (overlaps MMA tail)
        if (it < 2) {
            ld_a(x, it + 2, r0, tid, ra);
            ld_b(Wq, Wk, Wv, it + 2, tid, rb);
        }
        __syncthreads();
    }

    // epilogue: fragments -> g_Q (fp32+bias) / g_Kb (bf16 pairs+bias) / g_V
    const int grp = lane >> 2;
    const int qid = lane & 3;
    #pragma unroll
    for (int mt = 0; mt < 2; mt++) {
        int row0 = r0 + wm * 32 + mt * 16 + grp;
        #pragma unroll
        for (int nt = 0; nt < 6; nt++) {
            int cb  = wn * 48 + nt * 8;
            int h   = cb >> 6;
            int hc0 = (cb & 63) + qid * 2;
            if (h == 0) {
                float b0 = bq[hc0], b1 = bq[hc0 + 1];
                *(float2*)&g_Q[row0 * H_DIM + hc0] =
                    make_float2(acc[mt][nt][0] + b0, acc[mt][nt][1] + b1);
                *(float2*)&g_Q[(row0 + 8) * H_DIM + hc0] =
                    make_float2(acc[mt][nt][2] + b0, acc[mt][nt][3] + b1);
            } else if (h == 1) {
                float b0 = bk[hc0], b1 = bk[hc0 + 1];
                int pr = hc0 >> 1;
                __nv_bfloat162 k0 = __floats2bfloat162_rn(acc[mt][nt][0] + b0,
                                                          acc[mt][nt][1] + b1);
                __nv_bfloat162 k1 = __floats2bfloat162_rn(acc[mt][nt][2] + b0,
                                                          acc[mt][nt][3] + b1);
                g_Kb[row0 * 32 + pr]       = *(uint32_t*)&k0;
                g_Kb[(row0 + 8) * 32 + pr] = *(uint32_t*)&k1;
            } else {
                *(float2*)&g_V[row0 * H_DIM + hc0] =
                    make_float2(acc[mt][nt][0], acc[mt][nt][1]);
                *(float2*)&g_V[(row0 + 8) * H_DIM + hc0] =
                    make_float2(acc[mt][nt][2], acc[mt][nt][3]);
            }
        }
    }
}

// ===========================================================================
// Kernel 2: sparse attention with L1 window reuse. Shuffle-minimized:
//  - score phase: neighbor = 4p + (lane&3), chunk = lane>>2; reduction via
//    xor 4/8/16 lands the score directly in the owning lane (no broadcast).
//  - softmax without max-subtraction: |s| <= ~0.05 (scores are /512), so
//    exp(s) is safe and mathematically identical to the stabilized form.
// CTA = 896 threads (28 warps), 56 consecutive nodes, grid = 147 (~1/SM).
// ===========================================================================
__device__ __forceinline__ float qk_dot8(float4 q0, float4 q1, uint4 kd) {
    __nv_bfloat162 b;
    float2 f;
    float part;
    b = *(__nv_bfloat162*)&kd.x; f = __bfloat1622float2(b);
    part  = q0.x * f.x + q0.y * f.y;
    b = *(__nv_bfloat162*)&kd.y; f = __bfloat1622float2(b);
    part += q0.z * f.x + q0.w * f.y;
    b = *(__nv_bfloat162*)&kd.z; f = __bfloat1622float2(b);
    part += q1.x * f.x + q1.y * f.y;
    b = *(__nv_bfloat162*)&kd.w; f = __bfloat1622float2(b);
    part += q1.z * f.x + q1.w * f.y;
    return part;
}

#define ATT_WPB   28
#define ATT_NPC   56
#define ATT_GRID  ((N_NODES + ATT_NPC - 1) / ATT_NPC)

__global__ __launch_bounds__(ATT_WPB * 32) void attn_kernel(
    const int*   __restrict__ edge_index,   // [2, E]: src then dst
    const int*   __restrict__ edge_type,    // [E]
    const float* __restrict__ ek_table,     // [16]
    float*       __restrict__ out)          // [N, 64]
{
    const int lane = threadIdx.x & 31;
    const int w    = threadIdx.x >> 5;       // 0..27
    const int i0   = blockIdx.x * ATT_NPC;
    const int dc   = lane >> 2;               // 0..7: this lane's 8-dim chunk

    #pragma unroll
    for (int t = 0; t < 2; t++) {
        const int i = i0 + t * ATT_WPB + w;
        if (i >= N_NODES) break;              // warp-uniform guard
        const int e = i * DEG + lane;
        const int   j  = edge_index[E_EDGES + e];
        const float ek = ek_table[edge_type[e]];

        // lane loads Q dims dc*8 .. +7
        const float4* Qp = (const float4*)&g_Q[i * H_DIM + dc * 8];
        const float4 q0 = Qp[0], q1 = Qp[1];

        // scores: pass p covers neighbors 4p..4p+3 (lane&3 selects neighbor,
        // dc selects dim chunk); xor 4/8/16 reduce -> lane 4p+(lane&3) owns.
        float s = 0.f;
        #pragma unroll
        for (int pass = 0; pass < 8; pass++) {
            int n  = pass * 4 + (lane & 3);
            int jn = __shfl_sync(0xffffffffu, j, n);
            uint4 kd = *(const uint4*)&g_Kb[jn * 32 + dc * 4];
            float part = qk_dot8(q0, q1, kd);
            part += __shfl_xor_sync(0xffffffffu, part, 4);
            part += __shfl_xor_sync(0xffffffffu, part, 8);
            part += __shfl_xor_sync(0xffffffffu, part, 16);
            if (pass == dc) s = part;
        }
        s = (s + ek) * (1.0f / 512.0f);     // (/H) then (/sqrt(H)) = /512

        // softmax (no max-subtraction: |s| <= ~0.05)
        const float pexp = __expf(s);
        float sum = pexp;
        #pragma unroll
        for (int o = 16; o > 0; o >>= 1)
            sum += __shfl_xor_sync(0xffffffffu, sum, o);
        const float p = pexp / sum;

        // weighted V sum: lane owns dims 4c..4c+3 (c = lane&15);
        // half-warp g = lane>>4 processes neighbors 2t+g.
        const int c = lane & 15;
        const int g = lane >> 4;
        float4 a4 = make_float4(0.f, 0.f, 0.f, 0.f);
        #pragma unroll
        for (int n2 = 0; n2 < 16; n2++) {
            const int   n  = 2 * n2 + g;
            const float pn = __shfl_sync(0xffffffffu, p, n);
            const int   jn = __shfl_sync(0xffffffffu, j, n);
            const float4 v = *(const float4*)&g_V[jn * H_DIM + c * 4];
            a4.x += pn * v.x;
            a4.y += pn * v.y;
            a4.z += pn * v.z;
            a4.w += pn * v.w;
        }
        a4.x += __shfl_xor_sync(0xffffffffu, a4.x, 16);
        a4.y += __shfl_xor_sync(0xffffffffu, a4.y, 16);
        a4.z += __shfl_xor_sync(0xffffffffu, a4.z, 16);
        a4.w += __shfl_xor_sync(0xffffffffu, a4.w, 16);
        if (g == 0)
            *(float4*)&out[i * H_DIM + c * 4] = a4;
    }
}

// ---------------------------------------------------------------------------
extern "C" void kernel_launch(void* const* d_in, const int* in_sizes, int n_in,
                              void* d_out, int out_size)
{
    const float* x          = (const float*)d_in[0];
    // d_in[1] = adj — intentionally unused (edge list is exact)
    const int*   edge_index = (const int*)d_in[2];
    const int*   edge_type  = (const int*)d_in[3];
    const float* Wq         = (const float*)d_in[4];
    const float* bq         = (const float*)d_in[5];
    const float* Wk         = (const float*)d_in[6];
    const float* bk         = (const float*)d_in[7];
    const float* Wv         = (const float*)d_in[8];
    const float* ekt        = (const float*)d_in[9];
    float*       out        = (float*)d_out;

    static bool attr_set = false;
    if (!attr_set) {
        cudaFuncSetAttribute(qkv_mma_kernel,
                             cudaFuncAttributeMaxDynamicSharedMemorySize, QKV_SMEM);
        attr_set = true;
    }

    qkv_mma_kernel<<<N_NODES / 64, 256, QKV_SMEM>>>(x, Wq, bq, Wk, bk, Wv);
    attn_kernel<<<ATT_GRID, ATT_WPB * 32>>>(edge_index, edge_type, ekt, out);
}